// round 4
// baseline (speedup 1.0000x reference)
#include <cuda_runtime.h>
#include <cstdint>
#include <math.h>

// ---------------- problem constants ----------------
#define BB   16
#define NA   512
#define LA   1024
#define CD   128
#define GD   64
#define NH   4
#define LATD 128

// ---------------- device scratch ----------------
__device__ float    g_wcat [CD*NH*GD];
__device__ float    g_wh   [BB*NA*NH*GD];
__device__ float    g_src1 [NH*BB*NA];
__device__ float    g_dst1 [NH*BB*NA];
__device__ float    g_multi[BB*NA*NH*GD];
__device__ float    g_wh2  [BB*NA*CD];
__device__ float    g_src2 [BB*NA];
__device__ float    g_dst2 [BB*NA];
__device__ float    g_x    [BB*NA*CD];
__device__ float    g_wcT  [CD*LATD];
__device__ float    g_waT  [LATD*LATD];
__device__ float    g_avec [BB*NA*LATD];
__device__ float    g_pv0  [BB*LA*CD];
__device__ float    g_pv1  [BB*LA*CD];
__device__ float    g_comp [BB*LATD];
__device__ float    g_prot [BB*LATD];
__device__ unsigned g_adjbits[BB*NA*16];

__device__ __forceinline__ float lrelu_f(float x){ return x > 0.f ? x : 0.2f*x; }
__device__ __forceinline__ float elu_f(float x){ return x > 0.f ? x : (__expf(x) - 1.f); }

// ---------------- packed f32x2 helpers ----------------
#define FMA_F32X2(d, a, b) \
    asm("fma.rn.f32x2 %0, %1, %2, %0;" : "+l"(d) : "l"(a), "l"(b))
#define DUP_F32X2(d, s) \
    asm("mov.b64 %0, {%1, %1};" : "=l"(d) : "r"(s))
#define UNPACK_F32X2(lo, hi, v) \
    asm("mov.b64 {%0, %1}, %2;" : "=r"(lo), "=r"(hi) : "l"(v))

__device__ __forceinline__ float hsum_f32x2(unsigned long long v){
    uint32_t lo, hi; UNPACK_F32X2(lo, hi, v);
    return __uint_as_float(lo) + __uint_as_float(hi);
}

// ---------------- weight packing ----------------
__global__ void k_pack(const float* __restrict__ W_gat, const float* __restrict__ W_comp_w,
                       const float* __restrict__ W_att_w){
    int t = blockIdx.x*256 + threadIdx.x;
    if (t < CD*NH*GD){
        int k = t / (NH*GD), j = t % (NH*GD);
        int h = j / GD, f = j % GD;
        g_wcat[t] = W_gat[((size_t)h*CD + k)*GD + f];
    }
    if (t < CD*LATD){
        int k = t / LATD, l = t % LATD;
        g_wcT[t] = W_comp_w[(size_t)l*CD  + k];
        g_waT[t] = W_att_w [(size_t)l*LATD + k];
    }
}
__global__ void k_zero_acc(){
    int t = blockIdx.x*256 + threadIdx.x;
    if (t < BB*LATD){ g_comp[t] = 0.f; g_prot[t] = 0.f; }
}
__global__ void k_adjbits(const int* __restrict__ adj){
    int gid = blockIdx.x*256 + threadIdx.x;
    int v = adj[gid] > 0;
    unsigned m = __ballot_sync(0xffffffffu, v);
    if ((threadIdx.x & 31) == 0) g_adjbits[gid >> 5] = m;
}

// ---------------- tiled GEMM (f32x2, k-pair interleaved tiles) ----------------
__global__ __launch_bounds__(256) void k_gemm(
    const float* __restrict__ A, const float* __restrict__ Bm, float* __restrict__ C,
    int M, int N, int K, const float* __restrict__ bias, int act, const int* __restrict__ rowmap)
{
    __shared__ float As2[1024];     // [kp(8)][r(64)][2]
    __shared__ float Bs2[1024];     // [kp(8)][c(64)][2]
    int t = threadIdx.x;
    int row0 = blockIdx.y*64, col0 = blockIdx.x*64;
    int ty = t >> 4, tx = t & 15;
    unsigned long long acc2[4][4];
    #pragma unroll
    for (int i=0;i<4;i++)
        #pragma unroll
        for (int j=0;j<4;j++) acc2[i][j] = 0ull;

    for (int k0=0;k0<K;k0+=16){
        #pragma unroll
        for (int i=t;i<1024;i+=256){
            int r=i>>4, c=i&15;
            int ar = row0 + r;
            if (rowmap) ar = rowmap[ar];
            As2[((c>>1)*64 + r)*2 + (c&1)] = A[(size_t)ar*K + k0+c];
        }
        #pragma unroll
        for (int i=t;i<1024;i+=256){
            int r=i>>6, c=i&63;
            Bs2[((r>>1)*64 + c)*2 + (r&1)] = Bm[(size_t)(k0+r)*N + col0+c];
        }
        __syncthreads();
        #pragma unroll
        for (int kp=0;kp<8;kp++){
            ulonglong2 aA = *(const ulonglong2*)&As2[(kp*64 + ty*4)*2];
            ulonglong2 aB = *(const ulonglong2*)&As2[(kp*64 + ty*4 + 2)*2];
            ulonglong2 bA = *(const ulonglong2*)&Bs2[(kp*64 + tx*4)*2];
            ulonglong2 bB = *(const ulonglong2*)&Bs2[(kp*64 + tx*4 + 2)*2];
            unsigned long long av[4] = {aA.x, aA.y, aB.x, aB.y};
            unsigned long long bv[4] = {bA.x, bA.y, bB.x, bB.y};
            #pragma unroll
            for (int i=0;i<4;i++)
                #pragma unroll
                for (int j=0;j<4;j++) FMA_F32X2(acc2[i][j], av[i], bv[j]);
        }
        __syncthreads();
    }
    #pragma unroll
    for (int i=0;i<4;i++){
        int r = row0 + ty*4 + i;
        #pragma unroll
        for (int j=0;j<4;j++){
            int c = col0 + tx*4 + j;
            float v = hsum_f32x2(acc2[i][j]);
            if (bias) v += bias[c];
            if (act)  v = lrelu_f(v);
            C[(size_t)r*N + c] = v;
        }
    }
}

// ---------------- src/dst projections ----------------
__global__ __launch_bounds__(256) void k_srcdst1(const float* __restrict__ a_gat){
    __shared__ float as_[256], ad_[256];
    int t = threadIdx.x;
    { int h = t >> 6, f = t & 63;
      as_[t] = a_gat[h*2*GD + f];
      ad_[t] = a_gat[h*2*GD + GD + f]; }
    __syncthreads();
    int wid = t >> 5, lane = t & 31;
    int row = blockIdx.x*8 + wid;
    const float* wr = g_wh + (size_t)row*(NH*GD);
    float4 v0 = *(const float4*)&wr[4*lane];
    float4 v1 = *(const float4*)&wr[128 + 4*lane];
    const float* p0 = (const float*)&v0; const float* p1 = (const float*)&v1;
    float s0=0.f,d0=0.f,s1=0.f,d1=0.f;
    #pragma unroll
    for (int k=0;k<4;k++){
        int e = 4*lane + k;
        s0 += p0[k]*as_[e];       d0 += p0[k]*ad_[e];
        s1 += p1[k]*as_[128+e];   d1 += p1[k]*ad_[128+e];
    }
    #pragma unroll
    for (int o=8;o;o>>=1){
        s0 += __shfl_xor_sync(0xffffffffu,s0,o); d0 += __shfl_xor_sync(0xffffffffu,d0,o);
        s1 += __shfl_xor_sync(0xffffffffu,s1,o); d1 += __shfl_xor_sync(0xffffffffu,d1,o);
    }
    if ((lane & 15) == 0){
        int hA = lane >> 4;
        g_src1[(size_t)hA*BB*NA + row]     = s0;  g_dst1[(size_t)hA*BB*NA + row]     = d0;
        g_src1[(size_t)(2+hA)*BB*NA + row] = s1;  g_dst1[(size_t)(2+hA)*BB*NA + row] = d1;
    }
}
__global__ __launch_bounds__(256) void k_srcdst2(const float* __restrict__ a_go){
    __shared__ float ag[256];
    int t = threadIdx.x;
    ag[t] = a_go[t];
    __syncthreads();
    int wid = t >> 5, lane = t & 31;
    int row = blockIdx.x*8 + wid;
    float4 v = *(const float4*)&g_wh2[(size_t)row*CD + 4*lane];
    const float* p = (const float*)&v;
    float s=0.f, d=0.f;
    #pragma unroll
    for (int k=0;k<4;k++){ int e = 4*lane+k; s += p[k]*ag[e]; d += p[k]*ag[128+e]; }
    #pragma unroll
    for (int o=16;o;o>>=1){ s += __shfl_xor_sync(0xffffffffu,s,o); d += __shfl_xor_sync(0xffffffffu,d,o); }
    if (lane==0){ g_src2[row] = s; g_dst2[row] = d; }
}

// ---------------- fused GAT attention (f32x2 AV, j-pair interleaved Wh tile) ----------------
template<int FDIM>
__global__ __launch_bounds__(256) void k_attn(
    const float* __restrict__ Wh, int whStride,
    const float* __restrict__ src, const float* __restrict__ dst, int headStride,
    float* __restrict__ out, int outStride)
{
    constexpr int FG  = FDIM / 4;        // float4 groups per row
    constexpr int RP  = FDIM / 32;       // rows per thread (2 or 4)
    extern __shared__ float sm[];
    float* w    = sm;                    // [32][512] score rows
    float* whs  = w + 32*NA;             // j-pair interleaved: [16 pairs][FDIM][2]
    float* dsts = whs + 32*FDIM;         // [512]
    float* zz   = dsts + NA;             // [32]

    const int b = blockIdx.y, h = blockIdx.z;
    const int row0 = blockIdx.x * 32;
    const int t = threadIdx.x;
    const int wid = t >> 5, lane = t & 31;

    const float* srcp = src + (size_t)h*headStride + (size_t)b*NA;
    const float* dstp = dst + (size_t)h*headStride + (size_t)b*NA;
    const float* whp  = Wh  + (size_t)b*NA*whStride + h*GD;
    float*       outp = out + ((size_t)b*NA + row0)*outStride + h*GD;

    for (int j=t; j<NA; j+=256) dsts[j] = dstp[j];
    __syncthreads();

    // fused mask + leaky + exp + row-sum
    const unsigned* bitsbase = g_adjbits + (size_t)(b*NA + row0)*16;
    #pragma unroll
    for (int rr=0; rr<4; rr++){
        int r = wid*4 + rr;
        float srcv = srcp[row0 + r];
        const unsigned* br = bitsbase + (size_t)r*16;
        float s = 0.f;
        #pragma unroll
        for (int it=0; it<16; it++){
            unsigned m = br[it];
            int j = it*32 + lane;
            float e = srcv + dsts[j];
            e = e > 0.f ? e : 0.2f*e;
            float ev = ((m >> lane) & 1u) ? __expf(e) : 0.f;
            w[r*NA + j] = ev;
            s += ev;
        }
        #pragma unroll
        for (int o=16;o;o>>=1) s += __shfl_xor_sync(0xffffffffu,s,o);
        if (lane==0) zz[r] = 1.f / s;
    }

    // AV: [32 x 512] @ [512 x FDIM], f32x2 over j-pairs (lanes = even/odd j)
    const int fgrp = t % FG, rgrp = t / FG;
    const int fbase = fgrp*4, rbase = rgrp*RP;
    unsigned long long acc2[RP][4];
    #pragma unroll
    for (int i=0;i<RP;i++)
        #pragma unroll
        for (int c=0;c<4;c++) acc2[i][c] = 0ull;

    for (int jt=0; jt<NA; jt+=32){
        __syncthreads();
        #pragma unroll
        for (int i=t; i<32*FG; i+=256){
            int row = i / FG, c4 = i % FG;
            float4 v = *(const float4*)&whp[(size_t)(jt+row)*whStride + c4*4];
            int base = (row>>1)*FDIM*2 + (row&1);
            whs[base + (c4*4+0)*2] = v.x;
            whs[base + (c4*4+1)*2] = v.y;
            whs[base + (c4*4+2)*2] = v.z;
            whs[base + (c4*4+3)*2] = v.w;
        }
        __syncthreads();
        #pragma unroll
        for (int jj4=0; jj4<8; jj4++){
            int jp0 = jj4*2;
            ulonglong2 bA = *(const ulonglong2*)&whs[(jp0*FDIM + fbase)*2];
            ulonglong2 bB = *(const ulonglong2*)&whs[(jp0*FDIM + fbase + 2)*2];
            ulonglong2 cA = *(const ulonglong2*)&whs[((jp0+1)*FDIM + fbase)*2];
            ulonglong2 cB = *(const ulonglong2*)&whs[((jp0+1)*FDIM + fbase + 2)*2];
            #pragma unroll
            for (int i=0;i<RP;i++){
                ulonglong2 a2 = *(const ulonglong2*)&w[(rbase+i)*NA + jt + jj4*4];
                FMA_F32X2(acc2[i][0], a2.x, bA.x);
                FMA_F32X2(acc2[i][1], a2.x, bA.y);
                FMA_F32X2(acc2[i][2], a2.x, bB.x);
                FMA_F32X2(acc2[i][3], a2.x, bB.y);
                FMA_F32X2(acc2[i][0], a2.y, cA.x);
                FMA_F32X2(acc2[i][1], a2.y, cA.y);
                FMA_F32X2(acc2[i][2], a2.y, cB.x);
                FMA_F32X2(acc2[i][3], a2.y, cB.y);
            }
        }
    }
    #pragma unroll
    for (int i=0;i<RP;i++){
        float inv = zz[rbase+i];
        float4 o;
        o.x = elu_f(hsum_f32x2(acc2[i][0])*inv);
        o.y = elu_f(hsum_f32x2(acc2[i][1])*inv);
        o.z = elu_f(hsum_f32x2(acc2[i][2])*inv);
        o.w = elu_f(hsum_f32x2(acc2[i][3])*inv);
        *(float4*)&outp[(size_t)(rbase+i)*outStride + fbase] = o;
    }
}

// ---------------- 11x11 SAME conv + relu (f32x2: 4y x 2x outputs/thread) ----------------
__global__ __launch_bounds__(256) void k_conv(
    const float* __restrict__ in, float* __restrict__ out,
    const float* __restrict__ wAll, const float* __restrict__ bAll, int layer,
    const int* __restrict__ aminoIdx, const float* __restrict__ E)
{
    __shared__ float til[42*84];     // [y 42][c 42][2] pairs (x, x+32)
    __shared__ float ws[121];
    int bx = blockIdx.x, by = blockIdx.y, bz = blockIdx.z;
    int tx = threadIdx.x, ty = threadIdx.y;
    int t = ty*32 + tx;
    if (t < 121) ws[t] = wAll[layer*121 + t];
    int x0 = bx*64 - 5, y0 = by*32 - 5;
    const float* inb = in + (size_t)bz*LA*CD;
    for (int idx=t; idx<42*74; idx+=256){
        int ly = idx/74, cc = idx%74;
        int gy = y0+ly, gx = x0+cc;
        float v = 0.f;
        if (gx>=0 && gx<CD && gy>=0 && gy<LA){
            if (aminoIdx) v = E[(size_t)aminoIdx[(size_t)bz*LA + gy]*CD + gx];
            else          v = inb[(size_t)gy*CD + gx];
        }
        if (cc < 42)  til[ly*84 + cc*2]            = v;
        if (cc >= 32) til[ly*84 + (cc-32)*2 + 1]   = v;
    }
    __syncthreads();
    unsigned long long acc2[4];
    { unsigned long long b2; DUP_F32X2(b2, __float_as_uint(bAll[layer]));
      acc2[0]=b2; acc2[1]=b2; acc2[2]=b2; acc2[3]=b2; }
    #pragma unroll
    for (int dx=0; dx<11; dx++){
        unsigned long long rv[14];
        #pragma unroll
        for (int i=0;i<14;i++)
            rv[i] = *(const unsigned long long*)&til[(ty*4+i)*84 + (tx+dx)*2];
        #pragma unroll
        for (int dy=0; dy<11; dy++){
            unsigned long long wv2;
            DUP_F32X2(wv2, __float_as_uint(ws[dy*11+dx]));
            #pragma unroll
            for (int q=0;q<4;q++) FMA_F32X2(acc2[q], rv[q+dy], wv2);
        }
    }
    float* ob = out + (size_t)bz*LA*CD;
    #pragma unroll
    for (int q=0;q<4;q++){
        uint32_t lo, hi; UNPACK_F32X2(lo, hi, acc2[q]);
        int y = by*32 + ty*4 + q;
        ob[(size_t)y*CD + bx*64 + tx]      = fmaxf(__uint_as_float(lo), 0.f);
        ob[(size_t)y*CD + bx*64 + tx + 32] = fmaxf(__uint_as_float(hi), 0.f);
    }
}

// ---------------- attention pool ----------------
__global__ __launch_bounds__(256) void k_pool(
    const float* __restrict__ vec, const float* __restrict__ mask,
    const float* __restrict__ ba, float* __restrict__ outAcc, int R)
{
    __shared__ float At[128*36];
    __shared__ float Bs[16*132];
    __shared__ float mks[32];
    int b = blockIdx.y, tile = blockIdx.x;
    int t = threadIdx.x;
    int ty = t >> 5, tx = t & 31;
    int r0 = tile*32;

    #pragma unroll
    for (int q=0;q<16;q++){
        int idx = q*256 + t;
        int r = idx >> 7, k = idx & 127;
        At[k*36 + r] = vec[((size_t)b*R + r0 + r)*LATD + k];
    }
    if (t < 32) mks[t] = mask[(size_t)b*R + r0 + t];

    float acc[4][4];
    #pragma unroll
    for (int i=0;i<4;i++){ acc[i][0]=0.f; acc[i][1]=0.f; acc[i][2]=0.f; acc[i][3]=0.f; }

    for (int k0=0; k0<LATD; k0+=16){
        __syncthreads();
        #pragma unroll
        for (int q=0;q<8;q++){
            int idx = q*256 + t;
            int kk = idx >> 7, f = idx & 127;
            Bs[kk*132 + f] = g_waT[(size_t)(k0+kk)*LATD + f];
        }
        __syncthreads();
        #pragma unroll
        for (int kk=0;kk<16;kk++){
            float4 a4 = *(const float4*)&At[(k0+kk)*36 + ty*4];
            float4 b4 = *(const float4*)&Bs[kk*132 + tx*4];
            const float* ap = (const float*)&a4; const float* bp = (const float*)&b4;
            #pragma unroll
            for (int i=0;i<4;i++)
                #pragma unroll
                for (int j=0;j<4;j++) acc[i][j] += ap[i]*bp[j];
        }
    }
    float4 bias4 = *(const float4*)&ba[tx*4];
    const float* bp = (const float*)&bias4;
    float part[4];
    #pragma unroll
    for (int c=0;c<4;c++){
        float s = 0.f;
        #pragma unroll
        for (int i=0;i<4;i++){
            float v = lrelu_f(acc[i][c] + bp[c]);
            s += v * mks[ty*4 + i];
        }
        part[c] = s;
    }
    __syncthreads();
    float* red = Bs;
    *(float4*)&red[ty*132 + tx*4] = make_float4(part[0], part[1], part[2], part[3]);
    __syncthreads();
    if (t < 128){
        float s = 0.f;
        #pragma unroll
        for (int g=0; g<8; g++) s += red[g*132 + t];
        atomicAdd(&outAcc[(size_t)b*LATD + t], s);
    }
}

// ---------------- final head ----------------
__global__ void k_final(const float* __restrict__ amask, const float* __restrict__ pmask,
                        const float* __restrict__ pw, const float* __restrict__ pb,
                        float* __restrict__ outp)
{
    int b = blockIdx.x, t = threadIdx.x;
    __shared__ float red[256];
    __shared__ float sums[2];
    float sa = 0.f;
    for (int i=t; i<NA; i+=256) sa += amask[(size_t)b*NA + i];
    red[t] = sa; __syncthreads();
    for (int o=128;o;o>>=1){ if (t<o) red[t] += red[t+o]; __syncthreads(); }
    if (t==0) sums[0] = red[0];
    __syncthreads();
    float sp = 0.f;
    for (int i=t; i<LA; i+=256) sp += pmask[(size_t)b*LA + i];
    red[t] = sp; __syncthreads();
    for (int o=128;o;o>>=1){ if (t<o) red[t] += red[t+o]; __syncthreads(); }
    if (t==0) sums[1] = red[0];
    __syncthreads();
    float v = (t < LATD) ? g_comp[(size_t)b*LATD + t] / sums[0]
                         : g_prot[(size_t)b*LATD + (t-LATD)] / sums[1];
    v = lrelu_f(lrelu_f(v));
    red[t] = v * pw[t]; __syncthreads();
    for (int o=128;o;o>>=1){ if (t<o) red[t] += red[t+o]; __syncthreads(); }
    if (t==0) outp[b] = red[0] + pb[0];
}

// ---------------- launch ----------------
extern "C" void kernel_launch(void* const* d_in, const int* in_sizes, int n_in,
                              void* d_out, int out_size)
{
    const int*   atoms      = (const int*)  d_in[0];
    const float* atoms_mask = (const float*)d_in[1];
    const int*   adjacency  = (const int*)  d_in[2];
    const int*   amino      = (const int*)  d_in[3];
    const float* amino_mask = (const float*)d_in[4];
    const float* E_atom     = (const float*)d_in[5];
    const float* E_amino    = (const float*)d_in[6];
    const float* W_gat      = (const float*)d_in[7];
    const float* a_gat      = (const float*)d_in[8];
    const float* W_go       = (const float*)d_in[9];
    const float* a_go       = (const float*)d_in[10];
    const float* W_comp_w   = (const float*)d_in[11];
    const float* W_comp_b   = (const float*)d_in[12];
    const float* conv_w     = (const float*)d_in[13];
    const float* conv_b     = (const float*)d_in[14];
    const float* W_att_w    = (const float*)d_in[15];
    const float* W_att_b    = (const float*)d_in[16];
    const float* pred_w     = (const float*)d_in[17];
    const float* pred_b     = (const float*)d_in[18];
    float* outp = (float*)d_out;

    float *p_wcat, *p_wh, *p_src1, *p_dst1, *p_multi, *p_wh2, *p_src2, *p_dst2;
    float *p_x, *p_wcT, *p_avec, *p_pv0, *p_pv1, *p_comp, *p_prot;
    cudaGetSymbolAddress((void**)&p_wcat,  g_wcat);
    cudaGetSymbolAddress((void**)&p_wh,    g_wh);
    cudaGetSymbolAddress((void**)&p_src1,  g_src1);
    cudaGetSymbolAddress((void**)&p_dst1,  g_dst1);
    cudaGetSymbolAddress((void**)&p_multi, g_multi);
    cudaGetSymbolAddress((void**)&p_wh2,   g_wh2);
    cudaGetSymbolAddress((void**)&p_src2,  g_src2);
    cudaGetSymbolAddress((void**)&p_dst2,  g_dst2);
    cudaGetSymbolAddress((void**)&p_x,     g_x);
    cudaGetSymbolAddress((void**)&p_wcT,   g_wcT);
    cudaGetSymbolAddress((void**)&p_avec,  g_avec);
    cudaGetSymbolAddress((void**)&p_pv0,   g_pv0);
    cudaGetSymbolAddress((void**)&p_pv1,   g_pv1);
    cudaGetSymbolAddress((void**)&p_comp,  g_comp);
    cudaGetSymbolAddress((void**)&p_prot,  g_prot);

    const int SM1 = (32*NA + 32*GD  + NA + 32) * 4;   // 75904 B
    const int SM2 = (32*NA + 32*CD  + NA + 32) * 4;   // 84096 B
    cudaFuncSetAttribute(k_attn<GD>, cudaFuncAttributeMaxDynamicSharedMemorySize, SM1);
    cudaFuncSetAttribute(k_attn<CD>, cudaFuncAttributeMaxDynamicSharedMemorySize, SM2);

    // prep
    k_pack<<<128, 256>>>(W_gat, W_comp_w, W_att_w);
    k_adjbits<<<BB*NA*NA/256, 256>>>(adjacency);

    // ---- atom path ----
    k_gemm<<<dim3(4,128), 256>>>(E_atom, p_wcat, p_wh, BB*NA, NH*GD, CD, nullptr, 0, atoms);
    k_srcdst1<<<BB*NA/8, 256>>>(a_gat);
    k_attn<GD><<<dim3(NA/32, BB, NH), 256, SM1>>>(p_wh, NH*GD, p_src1, p_dst1, BB*NA, p_multi, NH*GD);
    k_gemm<<<dim3(2,128), 256>>>(p_multi, W_go, p_wh2, BB*NA, CD, NH*GD, nullptr, 0, nullptr);
    k_srcdst2<<<BB*NA/8, 256>>>(a_go);
    k_attn<CD><<<dim3(NA/32, BB, 1), 256, SM2>>>(p_wh2, CD, p_src2, p_dst2, 0, p_x, CD);
    k_gemm<<<dim3(2,128), 256>>>(p_x, p_wcT, p_avec, BB*NA, LATD, CD, W_comp_b, 1, nullptr);

    // ---- amino path ----
    k_conv<<<dim3(2,32,BB), dim3(32,8)>>>(p_pv1, p_pv0, conv_w, conv_b, 0, amino, E_amino);
    k_conv<<<dim3(2,32,BB), dim3(32,8)>>>(p_pv0, p_pv1, conv_w, conv_b, 1, nullptr, nullptr);
    k_conv<<<dim3(2,32,BB), dim3(32,8)>>>(p_pv1, p_pv0, conv_w, conv_b, 2, nullptr, nullptr);

    // ---- pooling + head ----
    k_zero_acc<<<8, 256>>>();
    k_pool<<<dim3(NA/32, BB), 256>>>(p_avec, atoms_mask, W_att_b, p_comp, NA);
    k_pool<<<dim3(LA/32, BB), 256>>>(p_pv0,  amino_mask, W_att_b, p_prot, LA);
    k_final<<<BB, 256>>>(atoms_mask, amino_mask, pred_w, pred_b, outp);
}

// round 5
// speedup vs baseline: 1.3434x; 1.3434x over previous
#include <cuda_runtime.h>
#include <cstdint>
#include <math.h>

// ---------------- problem constants ----------------
#define BB   16
#define NA   512
#define LA   1024
#define CD   128
#define GD   64
#define NH   4
#define LATD 128
#define BN   (BB*NA)

// ---------------- device scratch ----------------
__device__ float    g_wcat [CD*NH*GD];
__device__ float    g_wh   [BN*NH*GD];
__device__ float    g_src1 [NH*BN];
__device__ float    g_dst1 [NH*BN];
__device__ float    g_multi[BN*NH*GD];
__device__ float    g_wh2  [BN*CD];
__device__ float    g_src2 [BN];
__device__ float    g_dst2 [BN];
__device__ float    g_x    [BN*CD];
__device__ float    g_wcT  [CD*LATD];
__device__ float    g_waT  [LATD*LATD];
__device__ float    g_avec [BN*LATD];
__device__ float    g_pv0  [BB*LA*CD];
__device__ float    g_pv1  [BB*LA*CD];
__device__ float    g_comp [BB*LATD];
__device__ float    g_prot [BB*LATD];
__device__ unsigned g_adjbits[BN*16];

__device__ __forceinline__ float lrelu_f(float x){ return x > 0.f ? x : 0.2f*x; }
__device__ __forceinline__ float elu_f(float x){ return x > 0.f ? x : (__expf(x) - 1.f); }

// ---------------- weight packing ----------------
__global__ void k_pack(const float* __restrict__ W_gat, const float* __restrict__ W_comp_w,
                       const float* __restrict__ W_att_w){
    int t = blockIdx.x*256 + threadIdx.x;
    if (t < CD*NH*GD){
        int k = t / (NH*GD), j = t % (NH*GD);
        int h = j / GD, f = j % GD;
        g_wcat[t] = W_gat[((size_t)h*CD + k)*GD + f];
    }
    if (t < CD*LATD){
        int k = t / LATD, l = t % LATD;
        g_wcT[t] = W_comp_w[(size_t)l*CD  + k];
        g_waT[t] = W_att_w [(size_t)l*LATD + k];
    }
}
__global__ void k_zero_acc(){
    int t = blockIdx.x*256 + threadIdx.x;
    if (t < BB*LATD){ g_comp[t] = 0.f; g_prot[t] = 0.f; }
}
__global__ void k_adjbits(const int* __restrict__ adj){
    int gid = blockIdx.x*256 + threadIdx.x;
    int v = adj[gid] > 0;
    unsigned m = __ballot_sync(0xffffffffu, v);
    if ((threadIdx.x & 31) == 0) g_adjbits[gid >> 5] = m;
}

// ---------------- tiled GEMM: C = A(MxK)@B(KxN) [+bias][lrelu], optional row gather ----------------
__global__ __launch_bounds__(256) void k_gemm(
    const float* __restrict__ A, const float* __restrict__ Bm, float* __restrict__ C,
    int M, int N, int K, const float* __restrict__ bias, int act, const int* __restrict__ rowmap)
{
    __shared__ float As[16][68];
    __shared__ float Bs[16][64];
    int t = threadIdx.x;
    int row0 = blockIdx.y*64, col0 = blockIdx.x*64;
    int ty = t >> 4, tx = t & 15;
    float acc[4][4];
    #pragma unroll
    for (int i=0;i<4;i++){ acc[i][0]=0.f; acc[i][1]=0.f; acc[i][2]=0.f; acc[i][3]=0.f; }
    for (int k0=0;k0<K;k0+=16){
        #pragma unroll
        for (int i=t;i<1024;i+=256){
            int r=i>>4, c=i&15;
            int ar = row0 + r;
            if (rowmap) ar = rowmap[ar];
            As[c][r] = A[(size_t)ar*K + k0+c];
        }
        #pragma unroll
        for (int i=t;i<1024;i+=256){ int r=i>>6, c=i&63; Bs[r][c] = Bm[(size_t)(k0+r)*N + col0+c]; }
        __syncthreads();
        #pragma unroll
        for (int kk=0;kk<16;kk++){
            float4 a4 = *(const float4*)&As[kk][ty*4];
            float4 b4 = *(const float4*)&Bs[kk][tx*4];
            const float* ap = (const float*)&a4;
            const float* bp = (const float*)&b4;
            #pragma unroll
            for (int i=0;i<4;i++)
                #pragma unroll
                for (int j=0;j<4;j++) acc[i][j] += ap[i]*bp[j];
        }
        __syncthreads();
    }
    #pragma unroll
    for (int i=0;i<4;i++){
        int r = row0 + ty*4 + i;
        #pragma unroll
        for (int j=0;j<4;j++){
            int c = col0 + tx*4 + j;
            float v = acc[i][j];
            if (bias) v += bias[c];
            if (act)  v = lrelu_f(v);
            C[(size_t)r*N + c] = v;
        }
    }
}

// ---------------- src/dst projections (warp per row) ----------------
__global__ __launch_bounds__(256) void k_srcdst1(const float* __restrict__ a_gat){
    __shared__ float as_[256], ad_[256];
    int t = threadIdx.x;
    { int h = t >> 6, f = t & 63;
      as_[t] = a_gat[h*2*GD + f];
      ad_[t] = a_gat[h*2*GD + GD + f]; }
    __syncthreads();
    int wid = t >> 5, lane = t & 31;
    int row = blockIdx.x*8 + wid;
    const float* wr = g_wh + (size_t)row*(NH*GD);
    float4 v0 = *(const float4*)&wr[4*lane];
    float4 v1 = *(const float4*)&wr[128 + 4*lane];
    const float* p0 = (const float*)&v0; const float* p1 = (const float*)&v1;
    float s0=0.f,d0=0.f,s1=0.f,d1=0.f;
    #pragma unroll
    for (int k=0;k<4;k++){
        int e = 4*lane + k;
        s0 += p0[k]*as_[e];       d0 += p0[k]*ad_[e];
        s1 += p1[k]*as_[128+e];   d1 += p1[k]*ad_[128+e];
    }
    #pragma unroll
    for (int o=8;o;o>>=1){
        s0 += __shfl_xor_sync(0xffffffffu,s0,o); d0 += __shfl_xor_sync(0xffffffffu,d0,o);
        s1 += __shfl_xor_sync(0xffffffffu,s1,o); d1 += __shfl_xor_sync(0xffffffffu,d1,o);
    }
    if ((lane & 15) == 0){
        int hA = lane >> 4;
        g_src1[(size_t)hA*BN + row]     = s0;  g_dst1[(size_t)hA*BN + row]     = d0;
        g_src1[(size_t)(2+hA)*BN + row] = s1;  g_dst1[(size_t)(2+hA)*BN + row] = d1;
    }
}
__global__ __launch_bounds__(256) void k_srcdst2(const float* __restrict__ a_go){
    __shared__ float ag[256];
    int t = threadIdx.x;
    ag[t] = a_go[t];
    __syncthreads();
    int wid = t >> 5, lane = t & 31;
    int row = blockIdx.x*8 + wid;
    float4 v = *(const float4*)&g_wh2[(size_t)row*CD + 4*lane];
    const float* p = (const float*)&v;
    float s=0.f, d=0.f;
    #pragma unroll
    for (int k=0;k<4;k++){ int e = 4*lane+k; s += p[k]*ag[e]; d += p[k]*ag[128+e]; }
    #pragma unroll
    for (int o=16;o;o>>=1){ s += __shfl_xor_sync(0xffffffffu,s,o); d += __shfl_xor_sync(0xffffffffu,d,o); }
    if (lane==0){ g_src2[row] = s; g_dst2[row] = d; }
}

// ---------------- fused GAT attention (32 rows/block, bitmask adj, reg-tiled AV) ----------------
template<int FDIM>
__global__ __launch_bounds__(256) void k_attn(
    const float* __restrict__ Wh, int whStride,
    const float* __restrict__ src, const float* __restrict__ dst, int headStride,
    float* __restrict__ out, int outStride)
{
    constexpr int PAD = FDIM + 4;
    constexpr int FG  = FDIM / 4;
    constexpr int RP  = FDIM / 32;
    extern __shared__ float sm[];
    float* w    = sm;                    // [32][512]
    float* whs  = w + 32*NA;             // [32][PAD]
    float* dsts = whs + 32*PAD;          // [512]
    float* zz   = dsts + NA;             // [32]

    const int b = blockIdx.y, h = blockIdx.z;
    const int row0 = blockIdx.x * 32;
    const int t = threadIdx.x;
    const int wid = t >> 5, lane = t & 31;

    const float* srcp = src + (size_t)h*headStride + (size_t)b*NA;
    const float* dstp = dst + (size_t)h*headStride + (size_t)b*NA;
    const float* whp  = Wh  + (size_t)b*NA*whStride + h*GD;
    float*       outp = out + ((size_t)b*NA + row0)*outStride + h*GD;

    for (int j=t; j<NA; j+=256) dsts[j] = dstp[j];
    __syncthreads();

    const unsigned* bitsbase = g_adjbits + (size_t)(b*NA + row0)*16;
    #pragma unroll
    for (int rr=0; rr<4; rr++){
        int r = wid*4 + rr;
        float srcv = srcp[row0 + r];
        const unsigned* br = bitsbase + (size_t)r*16;
        float s = 0.f;
        #pragma unroll
        for (int it=0; it<16; it++){
            unsigned m = br[it];
            int j = it*32 + lane;
            float e = srcv + dsts[j];
            e = e > 0.f ? e : 0.2f*e;
            float ev = ((m >> lane) & 1u) ? __expf(e) : 0.f;
            w[r*NA + j] = ev;
            s += ev;
        }
        #pragma unroll
        for (int o=16;o;o>>=1) s += __shfl_xor_sync(0xffffffffu,s,o);
        if (lane==0) zz[r] = 1.f / s;
    }

    const int fgrp = t % FG, rgrp = t / FG;
    const int fbase = fgrp*4, rbase = rgrp*RP;
    float acc[RP][4];
    #pragma unroll
    for (int i=0;i<RP;i++){ acc[i][0]=0.f; acc[i][1]=0.f; acc[i][2]=0.f; acc[i][3]=0.f; }

    for (int jt=0; jt<NA; jt+=32){
        __syncthreads();
        #pragma unroll
        for (int i=t; i<32*FG; i+=256){
            int row = i / FG, c4 = i % FG;
            *(float4*)&whs[row*PAD + c4*4] =
                *(const float4*)&whp[(size_t)(jt+row)*whStride + c4*4];
        }
        __syncthreads();
        #pragma unroll
        for (int jj4=0; jj4<8; jj4++){
            float4 B0 = *(const float4*)&whs[(jj4*4+0)*PAD + fbase];
            float4 B1 = *(const float4*)&whs[(jj4*4+1)*PAD + fbase];
            float4 B2 = *(const float4*)&whs[(jj4*4+2)*PAD + fbase];
            float4 B3 = *(const float4*)&whs[(jj4*4+3)*PAD + fbase];
            const float* b0 = (const float*)&B0; const float* b1 = (const float*)&B1;
            const float* b2 = (const float*)&B2; const float* b3 = (const float*)&B3;
            #pragma unroll
            for (int i=0;i<RP;i++){
                float4 A4 = *(const float4*)&w[(rbase+i)*NA + jt + jj4*4];
                #pragma unroll
                for (int c=0;c<4;c++)
                    acc[i][c] += A4.x*b0[c] + A4.y*b1[c] + A4.z*b2[c] + A4.w*b3[c];
            }
        }
    }
    #pragma unroll
    for (int i=0;i<RP;i++){
        float inv = zz[rbase+i];
        float4 o;
        o.x = elu_f(acc[i][0]*inv); o.y = elu_f(acc[i][1]*inv);
        o.z = elu_f(acc[i][2]*inv); o.w = elu_f(acc[i][3]*inv);
        *(float4*)&outp[(size_t)(rbase+i)*outStride + fbase] = o;
    }
}

// ---------------- 11x11 SAME conv + relu, 4 outputs/thread, optional embedding gather ----------------
__global__ __launch_bounds__(256) void k_conv(
    const float* __restrict__ in, float* __restrict__ out,
    const float* __restrict__ wAll, const float* __restrict__ bAll, int layer,
    const int* __restrict__ aminoIdx, const float* __restrict__ E)
{
    __shared__ float tile[42][44];
    __shared__ float ws[121];
    int bx = blockIdx.x, by = blockIdx.y, bz = blockIdx.z;
    int tx = threadIdx.x, ty = threadIdx.y;
    int t = ty*32 + tx;
    if (t < 121) ws[t] = wAll[layer*121 + t];
    int x0 = bx*32 - 5, y0 = by*32 - 5;
    const float* inb = in + (size_t)bz*LA*CD;
    for (int idx=t; idx<42*42; idx+=256){
        int ly = idx/42, lx = idx%42;
        int gy = y0+ly, gx = x0+lx;
        float v = 0.f;
        if (gx>=0 && gx<CD && gy>=0 && gy<LA){
            if (aminoIdx) v = E[(size_t)aminoIdx[(size_t)bz*LA + gy]*CD + gx];
            else          v = inb[(size_t)gy*CD + gx];
        }
        tile[ly][lx] = v;
    }
    __syncthreads();
    float bb = bAll[layer];
    float acc[4] = {bb, bb, bb, bb};
    #pragma unroll
    for (int dx=0; dx<11; dx++){
        float rv[14];
        #pragma unroll
        for (int i=0;i<14;i++) rv[i] = tile[ty*4 + i][tx + dx];
        #pragma unroll
        for (int dy=0; dy<11; dy++){
            float wv = ws[dy*11 + dx];
            #pragma unroll
            for (int q=0;q<4;q++) acc[q] += rv[q+dy]*wv;
        }
    }
    #pragma unroll
    for (int q=0;q<4;q++)
        out[(size_t)bz*LA*CD + (size_t)(by*32 + ty*4 + q)*CD + bx*32 + tx] = fmaxf(acc[q], 0.f);
}

// ---------------- attention pool: sum_r mask_r * lrelu(vec_r @ Wa^T + b) ----------------
__global__ __launch_bounds__(256) void k_pool(
    const float* __restrict__ vec, const float* __restrict__ mask,
    const float* __restrict__ ba, float* __restrict__ outAcc, int R)
{
    __shared__ float At[128*36];
    __shared__ float Bs[16*132];
    __shared__ float mks[32];
    int b = blockIdx.y, tile = blockIdx.x;
    int t = threadIdx.x;
    int ty = t >> 5, tx = t & 31;
    int r0 = tile*32;

    #pragma unroll
    for (int q=0;q<16;q++){
        int idx = q*256 + t;
        int r = idx >> 7, k = idx & 127;
        At[k*36 + r] = vec[((size_t)b*R + r0 + r)*LATD + k];
    }
    if (t < 32) mks[t] = mask[(size_t)b*R + r0 + t];

    float acc[4][4];
    #pragma unroll
    for (int i=0;i<4;i++){ acc[i][0]=0.f; acc[i][1]=0.f; acc[i][2]=0.f; acc[i][3]=0.f; }

    for (int k0=0; k0<LATD; k0+=16){
        __syncthreads();
        #pragma unroll
        for (int q=0;q<8;q++){
            int idx = q*256 + t;
            int kk = idx >> 7, f = idx & 127;
            Bs[kk*132 + f] = g_waT[(size_t)(k0+kk)*LATD + f];
        }
        __syncthreads();
        #pragma unroll
        for (int kk=0;kk<16;kk++){
            float4 a4 = *(const float4*)&At[(k0+kk)*36 + ty*4];
            float4 b4 = *(const float4*)&Bs[kk*132 + tx*4];
            const float* ap = (const float*)&a4; const float* bp = (const float*)&b4;
            #pragma unroll
            for (int i=0;i<4;i++)
                #pragma unroll
                for (int j=0;j<4;j++) acc[i][j] += ap[i]*bp[j];
        }
    }
    float4 bias4 = *(const float4*)&ba[tx*4];
    const float* bp = (const float*)&bias4;
    float part[4];
    #pragma unroll
    for (int c=0;c<4;c++){
        float s = 0.f;
        #pragma unroll
        for (int i=0;i<4;i++){
            float v = lrelu_f(acc[i][c] + bp[c]);
            s += v * mks[ty*4 + i];
        }
        part[c] = s;
    }
    __syncthreads();
    float* red = Bs;
    *(float4*)&red[ty*132 + tx*4] = make_float4(part[0], part[1], part[2], part[3]);
    __syncthreads();
    if (t < 128){
        float s = 0.f;
        #pragma unroll
        for (int g=0; g<8; g++) s += red[g*132 + t];
        atomicAdd(&outAcc[(size_t)b*LATD + t], s);
    }
}

// ---------------- final head ----------------
__global__ void k_final(const float* __restrict__ amask, const float* __restrict__ pmask,
                        const float* __restrict__ pw, const float* __restrict__ pb,
                        float* __restrict__ outp)
{
    int b = blockIdx.x, t = threadIdx.x;
    __shared__ float red[256];
    __shared__ float sums[2];
    float sa = 0.f;
    for (int i=t; i<NA; i+=256) sa += amask[(size_t)b*NA + i];
    red[t] = sa; __syncthreads();
    for (int o=128;o;o>>=1){ if (t<o) red[t] += red[t+o]; __syncthreads(); }
    if (t==0) sums[0] = red[0];
    __syncthreads();
    float sp = 0.f;
    for (int i=t; i<LA; i+=256) sp += pmask[(size_t)b*LA + i];
    red[t] = sp; __syncthreads();
    for (int o=128;o;o>>=1){ if (t<o) red[t] += red[t+o]; __syncthreads(); }
    if (t==0) sums[1] = red[0];
    __syncthreads();
    float v = (t < LATD) ? g_comp[(size_t)b*LATD + t] / sums[0]
                         : g_prot[(size_t)b*LATD + (t-LATD)] / sums[1];
    v = lrelu_f(lrelu_f(v));
    red[t] = v * pw[t]; __syncthreads();
    for (int o=128;o;o>>=1){ if (t<o) red[t] += red[t+o]; __syncthreads(); }
    if (t==0) outp[b] = red[0] + pb[0];
}

// ---------------- launch (2-stream fork/join: amino path overlaps atom path) ----------------
extern "C" void kernel_launch(void* const* d_in, const int* in_sizes, int n_in,
                              void* d_out, int out_size)
{
    const int*   atoms      = (const int*)  d_in[0];
    const float* atoms_mask = (const float*)d_in[1];
    const int*   adjacency  = (const int*)  d_in[2];
    const int*   amino      = (const int*)  d_in[3];
    const float* amino_mask = (const float*)d_in[4];
    const float* E_atom     = (const float*)d_in[5];
    const float* E_amino    = (const float*)d_in[6];
    const float* W_gat      = (const float*)d_in[7];
    const float* a_gat      = (const float*)d_in[8];
    const float* W_go       = (const float*)d_in[9];
    const float* a_go       = (const float*)d_in[10];
    const float* W_comp_w   = (const float*)d_in[11];
    const float* W_comp_b   = (const float*)d_in[12];
    const float* conv_w     = (const float*)d_in[13];
    const float* conv_b     = (const float*)d_in[14];
    const float* W_att_w    = (const float*)d_in[15];
    const float* W_att_b    = (const float*)d_in[16];
    const float* pred_w     = (const float*)d_in[17];
    const float* pred_b     = (const float*)d_in[18];
    float* outp = (float*)d_out;

    float *p_wcat, *p_wh, *p_src1, *p_dst1, *p_multi, *p_wh2, *p_src2, *p_dst2;
    float *p_x, *p_wcT, *p_avec, *p_pv0, *p_pv1, *p_comp, *p_prot;
    cudaGetSymbolAddress((void**)&p_wcat,  g_wcat);
    cudaGetSymbolAddress((void**)&p_wh,    g_wh);
    cudaGetSymbolAddress((void**)&p_src1,  g_src1);
    cudaGetSymbolAddress((void**)&p_dst1,  g_dst1);
    cudaGetSymbolAddress((void**)&p_multi, g_multi);
    cudaGetSymbolAddress((void**)&p_wh2,   g_wh2);
    cudaGetSymbolAddress((void**)&p_src2,  g_src2);
    cudaGetSymbolAddress((void**)&p_dst2,  g_dst2);
    cudaGetSymbolAddress((void**)&p_x,     g_x);
    cudaGetSymbolAddress((void**)&p_wcT,   g_wcT);
    cudaGetSymbolAddress((void**)&p_avec,  g_avec);
    cudaGetSymbolAddress((void**)&p_pv0,   g_pv0);
    cudaGetSymbolAddress((void**)&p_pv1,   g_pv1);
    cudaGetSymbolAddress((void**)&p_comp,  g_comp);
    cudaGetSymbolAddress((void**)&p_prot,  g_prot);

    const int SM1 = (32*NA + 32*(GD+4)  + NA + 32) * 4;   // 76416 B
    const int SM2 = (32*NA + 32*(CD+4)  + NA + 32) * 4;   // 84608 B
    cudaFuncSetAttribute(k_attn<GD>, cudaFuncAttributeMaxDynamicSharedMemorySize, SM1);
    cudaFuncSetAttribute(k_attn<CD>, cudaFuncAttributeMaxDynamicSharedMemorySize, SM2);

    // lazy side-stream / events (created on the uncaptured correctness call;
    // reused unchanged on the capture call — identical work every invocation)
    static cudaStream_t s2 = nullptr;
    static cudaEvent_t evFork = nullptr, evJoin = nullptr;
    if (!s2){
        cudaStreamCreateWithFlags(&s2, cudaStreamNonBlocking);
        cudaEventCreateWithFlags(&evFork, cudaEventDisableTiming);
        cudaEventCreateWithFlags(&evJoin, cudaEventDisableTiming);
    }

    // ---- common prep on main stream, then fork ----
    k_zero_acc<<<8, 256>>>();
    k_pack<<<128, 256>>>(W_gat, W_comp_w, W_att_w);
    cudaEventRecord(evFork, 0);
    cudaStreamWaitEvent(s2, evFork, 0);

    // ---- amino path on side stream ----
    k_conv<<<dim3(4,32,BB), dim3(32,8), 0, s2>>>(p_pv1, p_pv0, conv_w, conv_b, 0, amino, E_amino);
    k_conv<<<dim3(4,32,BB), dim3(32,8), 0, s2>>>(p_pv0, p_pv1, conv_w, conv_b, 1, nullptr, nullptr);
    k_conv<<<dim3(4,32,BB), dim3(32,8), 0, s2>>>(p_pv1, p_pv0, conv_w, conv_b, 2, nullptr, nullptr);
    k_pool<<<dim3(LA/32, BB), 256, 0, s2>>>(p_pv0, amino_mask, W_att_b, p_prot, LA);
    cudaEventRecord(evJoin, s2);

    // ---- atom path on main stream ----
    k_adjbits<<<BN*NA/256, 256>>>(adjacency);
    k_gemm<<<dim3(4,128), 256>>>(E_atom, p_wcat, p_wh, BN, NH*GD, CD, nullptr, 0, atoms);
    k_srcdst1<<<BN/8, 256>>>(a_gat);
    k_attn<GD><<<dim3(NA/32, BB, NH), 256, SM1>>>(p_wh, NH*GD, p_src1, p_dst1, BN, p_multi, NH*GD);
    k_gemm<<<dim3(2,128), 256>>>(p_multi, W_go, p_wh2, BN, CD, NH*GD, nullptr, 0, nullptr);
    k_srcdst2<<<BN/8, 256>>>(a_go);
    k_attn<CD><<<dim3(NA/32, BB, 1), 256, SM2>>>(p_wh2, CD, p_src2, p_dst2, 0, p_x, CD);
    k_gemm<<<dim3(2,128), 256>>>(p_x, p_wcT, p_avec, BN, LATD, CD, W_comp_b, 1, nullptr);
    k_pool<<<dim3(NA/32, BB), 256>>>(p_avec, atoms_mask, W_att_b, p_comp, NA);

    // ---- join + head ----
    cudaStreamWaitEvent(0, evJoin, 0);
    k_final<<<BB, 256>>>(atoms_mask, amino_mask, pred_w, pred_b, outp);
}

// round 6
// speedup vs baseline: 1.5477x; 1.1521x over previous
#include <cuda_runtime.h>
#include <cstdint>
#include <math.h>

// ---------------- problem constants ----------------
#define BB   16
#define NA   512
#define LA   1024
#define CD   128
#define GD   64
#define NH   4
#define LATD 128
#define BN   (BB*NA)

// ---------------- device scratch ----------------
__device__ float    g_wcat [CD*NH*GD];
__device__ float    g_wh   [BN*NH*GD];
__device__ float    g_src1 [NH*BN];
__device__ float    g_dst1 [NH*BN];
__device__ float    g_multi[BN*NH*GD];
__device__ float    g_wh2  [BN*CD];
__device__ float    g_src2 [BN];
__device__ float    g_dst2 [BN];
__device__ float    g_x    [BN*CD];
__device__ float    g_wcT  [CD*LATD];
__device__ float    g_waT  [LATD*LATD];
__device__ float    g_avec [BN*LATD];
__device__ float    g_pv0  [BB*LA*CD];
__device__ float    g_pv1  [BB*LA*CD];
__device__ float    g_comp [BB*LATD];
__device__ float    g_prot [BB*LATD];
__device__ unsigned g_adjbits[BN*16];

__device__ __forceinline__ float lrelu_f(float x){ return x > 0.f ? x : 0.2f*x; }
__device__ __forceinline__ float elu_f(float x){ return x > 0.f ? x : (__expf(x) - 1.f); }

// ---------------- weight packing ----------------
__global__ void k_pack(const float* __restrict__ W_gat, const float* __restrict__ W_comp_w,
                       const float* __restrict__ W_att_w){
    int t = blockIdx.x*256 + threadIdx.x;
    if (t < CD*NH*GD){
        int k = t / (NH*GD), j = t % (NH*GD);
        int h = j / GD, f = j % GD;
        g_wcat[t] = W_gat[((size_t)h*CD + k)*GD + f];
    }
    if (t < CD*LATD){
        int k = t / LATD, l = t % LATD;
        g_wcT[t] = W_comp_w[(size_t)l*CD  + k];
        g_waT[t] = W_att_w [(size_t)l*LATD + k];
    }
}
__global__ void k_zero_acc(){
    int t = blockIdx.x*256 + threadIdx.x;
    if (t < BB*LATD){ g_comp[t] = 0.f; g_prot[t] = 0.f; }
    if (t < BN){ g_src2[t] = 0.f; g_dst2[t] = 0.f; }
}
__global__ void k_adjbits(const int* __restrict__ adj){
    int gid = blockIdx.x*256 + threadIdx.x;
    int v = adj[gid] > 0;
    unsigned m = __ballot_sync(0xffffffffu, v);
    if ((threadIdx.x & 31) == 0) g_adjbits[gid >> 5] = m;
}

// ---------------- tiled GEMM + fused src/dst projection epilogue ----------------
// sdMode 0: plain.  1: N=256 Wh gemm — col block == head, write g_src1/g_dst1 direct.
//           2: N=128 W_go gemm — partial sums, atomicAdd into g_src2/g_dst2 (pre-zeroed).
__global__ __launch_bounds__(256) void k_gemm(
    const float* __restrict__ A, const float* __restrict__ Bm, float* __restrict__ C,
    int M, int N, int K, const float* __restrict__ bias, int act,
    const int* __restrict__ rowmap, const float* __restrict__ aVec, int sdMode)
{
    __shared__ float As[16][68];
    __shared__ float Bs[16][64];
    int t = threadIdx.x;
    int row0 = blockIdx.y*64, col0 = blockIdx.x*64;
    int ty = t >> 4, tx = t & 15;
    float acc[4][4];
    #pragma unroll
    for (int i=0;i<4;i++){ acc[i][0]=0.f; acc[i][1]=0.f; acc[i][2]=0.f; acc[i][3]=0.f; }
    for (int k0=0;k0<K;k0+=16){
        #pragma unroll
        for (int i=t;i<1024;i+=256){
            int r=i>>4, c=i&15;
            int ar = row0 + r;
            if (rowmap) ar = rowmap[ar];
            As[c][r] = A[(size_t)ar*K + k0+c];
        }
        #pragma unroll
        for (int i=t;i<1024;i+=256){ int r=i>>6, c=i&63; Bs[r][c] = Bm[(size_t)(k0+r)*N + col0+c]; }
        __syncthreads();
        #pragma unroll
        for (int kk=0;kk<16;kk++){
            float4 a4 = *(const float4*)&As[kk][ty*4];
            float4 b4 = *(const float4*)&Bs[kk][tx*4];
            const float* ap = (const float*)&a4;
            const float* bp = (const float*)&b4;
            #pragma unroll
            for (int i=0;i<4;i++)
                #pragma unroll
                for (int j=0;j<4;j++) acc[i][j] += ap[i]*bp[j];
        }
        __syncthreads();
    }
    #pragma unroll
    for (int i=0;i<4;i++){
        int r = row0 + ty*4 + i;
        #pragma unroll
        for (int j=0;j<4;j++){
            int c = col0 + tx*4 + j;
            float v = acc[i][j];
            if (bias) v += bias[c];
            if (act)  v = lrelu_f(v);
            C[(size_t)r*N + c] = v;
        }
    }
    if (sdMode){
        int c0 = tx*4;
        float4 as4, ad4;
        if (sdMode == 1){
            const float* aP = aVec + (size_t)(col0 >> 6)*128;   // head block
            as4 = *(const float4*)&aP[c0];
            ad4 = *(const float4*)&aP[64 + c0];
        } else {
            as4 = *(const float4*)&aVec[col0 + c0];
            ad4 = *(const float4*)&aVec[128 + col0 + c0];
        }
        #pragma unroll
        for (int i=0;i<4;i++){
            float s = acc[i][0]*as4.x + acc[i][1]*as4.y + acc[i][2]*as4.z + acc[i][3]*as4.w;
            float d = acc[i][0]*ad4.x + acc[i][1]*ad4.y + acc[i][2]*ad4.z + acc[i][3]*ad4.w;
            #pragma unroll
            for (int o=8;o;o>>=1){
                s += __shfl_xor_sync(0xffffffffu, s, o);
                d += __shfl_xor_sync(0xffffffffu, d, o);
            }
            if (tx == 0){
                int r = row0 + ty*4 + i;
                if (sdMode == 1){
                    int h = col0 >> 6;
                    g_src1[(size_t)h*BN + r] = s;
                    g_dst1[(size_t)h*BN + r] = d;
                } else {
                    atomicAdd(&g_src2[r], s);
                    atomicAdd(&g_dst2[r], d);
                }
            }
        }
    }
}

// ---------------- fused GAT attention (32 rows/block, bitmask adj, reg-tiled AV) ----------------
template<int FDIM>
__global__ __launch_bounds__(256) void k_attn(
    const float* __restrict__ Wh, int whStride,
    const float* __restrict__ src, const float* __restrict__ dst, int headStride,
    float* __restrict__ out, int outStride)
{
    constexpr int PAD = FDIM + 4;
    constexpr int FG  = FDIM / 4;
    constexpr int RP  = FDIM / 32;
    extern __shared__ float sm[];
    float* w    = sm;                    // [32][512]
    float* whs  = w + 32*NA;             // [32][PAD]
    float* dsts = whs + 32*PAD;          // [512]
    float* zz   = dsts + NA;             // [32]

    const int b = blockIdx.y, h = blockIdx.z;
    const int row0 = blockIdx.x * 32;
    const int t = threadIdx.x;
    const int wid = t >> 5, lane = t & 31;

    const float* srcp = src + (size_t)h*headStride + (size_t)b*NA;
    const float* dstp = dst + (size_t)h*headStride + (size_t)b*NA;
    const float* whp  = Wh  + (size_t)b*NA*whStride + h*GD;
    float*       outp = out + ((size_t)b*NA + row0)*outStride + h*GD;

    for (int j=t; j<NA; j+=256) dsts[j] = dstp[j];
    __syncthreads();

    const unsigned* bitsbase = g_adjbits + (size_t)(b*NA + row0)*16;
    #pragma unroll
    for (int rr=0; rr<4; rr++){
        int r = wid*4 + rr;
        float srcv = srcp[row0 + r];
        const unsigned* br = bitsbase + (size_t)r*16;
        float s = 0.f;
        #pragma unroll
        for (int it=0; it<16; it++){
            unsigned m = br[it];
            int j = it*32 + lane;
            float e = srcv + dsts[j];
            e = e > 0.f ? e : 0.2f*e;
            float ev = ((m >> lane) & 1u) ? __expf(e) : 0.f;
            w[r*NA + j] = ev;
            s += ev;
        }
        #pragma unroll
        for (int o=16;o;o>>=1) s += __shfl_xor_sync(0xffffffffu,s,o);
        if (lane==0) zz[r] = 1.f / s;
    }

    const int fgrp = t % FG, rgrp = t / FG;
    const int fbase = fgrp*4, rbase = rgrp*RP;
    float acc[RP][4];
    #pragma unroll
    for (int i=0;i<RP;i++){ acc[i][0]=0.f; acc[i][1]=0.f; acc[i][2]=0.f; acc[i][3]=0.f; }

    for (int jt=0; jt<NA; jt+=32){
        __syncthreads();
        #pragma unroll
        for (int i=t; i<32*FG; i+=256){
            int row = i / FG, c4 = i % FG;
            *(float4*)&whs[row*PAD + c4*4] =
                *(const float4*)&whp[(size_t)(jt+row)*whStride + c4*4];
        }
        __syncthreads();
        #pragma unroll
        for (int jj4=0; jj4<8; jj4++){
            float4 B0 = *(const float4*)&whs[(jj4*4+0)*PAD + fbase];
            float4 B1 = *(const float4*)&whs[(jj4*4+1)*PAD + fbase];
            float4 B2 = *(const float4*)&whs[(jj4*4+2)*PAD + fbase];
            float4 B3 = *(const float4*)&whs[(jj4*4+3)*PAD + fbase];
            const float* b0 = (const float*)&B0; const float* b1 = (const float*)&B1;
            const float* b2 = (const float*)&B2; const float* b3 = (const float*)&B3;
            #pragma unroll
            for (int i=0;i<RP;i++){
                float4 A4 = *(const float4*)&w[(rbase+i)*NA + jt + jj4*4];
                #pragma unroll
                for (int c=0;c<4;c++)
                    acc[i][c] += A4.x*b0[c] + A4.y*b1[c] + A4.z*b2[c] + A4.w*b3[c];
            }
        }
    }
    #pragma unroll
    for (int i=0;i<RP;i++){
        float inv = zz[rbase+i];
        float4 o;
        o.x = elu_f(acc[i][0]*inv); o.y = elu_f(acc[i][1]*inv);
        o.z = elu_f(acc[i][2]*inv); o.w = elu_f(acc[i][3]*inv);
        *(float4*)&outp[(size_t)(rbase+i)*outStride + fbase] = o;
    }
}

// ---------------- 11x11 SAME conv + relu, 8 y-outputs/thread ----------------
__global__ __launch_bounds__(256) void k_conv(
    const float* __restrict__ in, float* __restrict__ out,
    const float* __restrict__ wAll, const float* __restrict__ bAll, int layer,
    const int* __restrict__ aminoIdx, const float* __restrict__ E)
{
    __shared__ float tile[74][44];
    __shared__ float ws[121];
    int bx = blockIdx.x, by = blockIdx.y, bz = blockIdx.z;
    int tx = threadIdx.x, ty = threadIdx.y;       // 32 x 8
    int t = ty*32 + tx;
    if (t < 121) ws[t] = wAll[layer*121 + t];
    int x0 = bx*32 - 5, y0 = by*64 - 5;
    const float* inb = in + (size_t)bz*LA*CD;
    for (int idx=t; idx<74*42; idx+=256){
        int ly = idx/42, lx = idx%42;
        int gy = y0+ly, gx = x0+lx;
        float v = 0.f;
        if (gx>=0 && gx<CD && gy>=0 && gy<LA){
            if (aminoIdx) v = E[(size_t)aminoIdx[(size_t)bz*LA + gy]*CD + gx];
            else          v = inb[(size_t)gy*CD + gx];
        }
        tile[ly][lx] = v;
    }
    __syncthreads();
    float bb = bAll[layer];
    float acc[8];
    #pragma unroll
    for (int q=0;q<8;q++) acc[q] = bb;
    #pragma unroll
    for (int dx=0; dx<11; dx++){
        float rv[18];
        #pragma unroll
        for (int i=0;i<18;i++) rv[i] = tile[ty*8 + i][tx + dx];
        #pragma unroll
        for (int dy=0; dy<11; dy++){
            float wv = ws[dy*11 + dx];
            #pragma unroll
            for (int q=0;q<8;q++) acc[q] += rv[q+dy]*wv;
        }
    }
    float* ob = out + (size_t)bz*LA*CD + (size_t)(by*64 + ty*8)*CD + bx*32 + tx;
    #pragma unroll
    for (int q=0;q<8;q++)
        ob[(size_t)q*CD] = fmaxf(acc[q], 0.f);
}

// ---------------- attention pool: sum_r mask_r * lrelu(vec_r @ Wa^T + b) ----------------
__global__ __launch_bounds__(256) void k_pool(
    const float* __restrict__ vec, const float* __restrict__ mask,
    const float* __restrict__ ba, float* __restrict__ outAcc, int R)
{
    __shared__ float At[128*36];
    __shared__ float Bs[16*132];
    __shared__ float mks[32];
    int b = blockIdx.y, tile = blockIdx.x;
    int t = threadIdx.x;
    int ty = t >> 5, tx = t & 31;
    int r0 = tile*32;

    #pragma unroll
    for (int q=0;q<16;q++){
        int idx = q*256 + t;
        int r = idx >> 7, k = idx & 127;
        At[k*36 + r] = vec[((size_t)b*R + r0 + r)*LATD + k];
    }
    if (t < 32) mks[t] = mask[(size_t)b*R + r0 + t];

    float acc[4][4];
    #pragma unroll
    for (int i=0;i<4;i++){ acc[i][0]=0.f; acc[i][1]=0.f; acc[i][2]=0.f; acc[i][3]=0.f; }

    for (int k0=0; k0<LATD; k0+=16){
        __syncthreads();
        #pragma unroll
        for (int q=0;q<8;q++){
            int idx = q*256 + t;
            int kk = idx >> 7, f = idx & 127;
            Bs[kk*132 + f] = g_waT[(size_t)(k0+kk)*LATD + f];
        }
        __syncthreads();
        #pragma unroll
        for (int kk=0;kk<16;kk++){
            float4 a4 = *(const float4*)&At[(k0+kk)*36 + ty*4];
            float4 b4 = *(const float4*)&Bs[kk*132 + tx*4];
            const float* ap = (const float*)&a4; const float* bp = (const float*)&b4;
            #pragma unroll
            for (int i=0;i<4;i++)
                #pragma unroll
                for (int j=0;j<4;j++) acc[i][j] += ap[i]*bp[j];
        }
    }
    float4 bias4 = *(const float4*)&ba[tx*4];
    const float* bp = (const float*)&bias4;
    float part[4];
    #pragma unroll
    for (int c=0;c<4;c++){
        float s = 0.f;
        #pragma unroll
        for (int i=0;i<4;i++){
            float v = lrelu_f(acc[i][c] + bp[c]);
            s += v * mks[ty*4 + i];
        }
        part[c] = s;
    }
    __syncthreads();
    float* red = Bs;
    *(float4*)&red[ty*132 + tx*4] = make_float4(part[0], part[1], part[2], part[3]);
    __syncthreads();
    if (t < 128){
        float s = 0.f;
        #pragma unroll
        for (int g=0; g<8; g++) s += red[g*132 + t];
        atomicAdd(&outAcc[(size_t)b*LATD + t], s);
    }
}

// ---------------- final head ----------------
__global__ void k_final(const float* __restrict__ amask, const float* __restrict__ pmask,
                        const float* __restrict__ pw, const float* __restrict__ pb,
                        float* __restrict__ outp)
{
    int b = blockIdx.x, t = threadIdx.x;
    __shared__ float red[256];
    __shared__ float sums[2];
    float sa = 0.f;
    for (int i=t; i<NA; i+=256) sa += amask[(size_t)b*NA + i];
    red[t] = sa; __syncthreads();
    for (int o=128;o;o>>=1){ if (t<o) red[t] += red[t+o]; __syncthreads(); }
    if (t==0) sums[0] = red[0];
    __syncthreads();
    float sp = 0.f;
    for (int i=t; i<LA; i+=256) sp += pmask[(size_t)b*LA + i];
    red[t] = sp; __syncthreads();
    for (int o=128;o;o>>=1){ if (t<o) red[t] += red[t+o]; __syncthreads(); }
    if (t==0) sums[1] = red[0];
    __syncthreads();
    float v = (t < LATD) ? g_comp[(size_t)b*LATD + t] / sums[0]
                         : g_prot[(size_t)b*LATD + (t-LATD)] / sums[1];
    v = lrelu_f(lrelu_f(v));
    red[t] = v * pw[t]; __syncthreads();
    for (int o=128;o;o>>=1){ if (t<o) red[t] += red[t+o]; __syncthreads(); }
    if (t==0) outp[b] = red[0] + pb[0];
}

// ---------------- launch (2-stream fork/join) ----------------
extern "C" void kernel_launch(void* const* d_in, const int* in_sizes, int n_in,
                              void* d_out, int out_size)
{
    const int*   atoms      = (const int*)  d_in[0];
    const float* atoms_mask = (const float*)d_in[1];
    const int*   adjacency  = (const int*)  d_in[2];
    const int*   amino      = (const int*)  d_in[3];
    const float* amino_mask = (const float*)d_in[4];
    const float* E_atom     = (const float*)d_in[5];
    const float* E_amino    = (const float*)d_in[6];
    const float* W_gat      = (const float*)d_in[7];
    const float* a_gat      = (const float*)d_in[8];
    const float* W_go       = (const float*)d_in[9];
    const float* a_go       = (const float*)d_in[10];
    const float* W_comp_w   = (const float*)d_in[11];
    const float* W_comp_b   = (const float*)d_in[12];
    const float* conv_w     = (const float*)d_in[13];
    const float* conv_b     = (const float*)d_in[14];
    const float* W_att_w    = (const float*)d_in[15];
    const float* W_att_b    = (const float*)d_in[16];
    const float* pred_w     = (const float*)d_in[17];
    const float* pred_b     = (const float*)d_in[18];
    float* outp = (float*)d_out;

    float *p_wcat, *p_wh, *p_src1, *p_dst1, *p_multi, *p_wh2, *p_src2, *p_dst2;
    float *p_x, *p_wcT, *p_avec, *p_pv0, *p_pv1, *p_comp, *p_prot;
    cudaGetSymbolAddress((void**)&p_wcat,  g_wcat);
    cudaGetSymbolAddress((void**)&p_wh,    g_wh);
    cudaGetSymbolAddress((void**)&p_src1,  g_src1);
    cudaGetSymbolAddress((void**)&p_dst1,  g_dst1);
    cudaGetSymbolAddress((void**)&p_multi, g_multi);
    cudaGetSymbolAddress((void**)&p_wh2,   g_wh2);
    cudaGetSymbolAddress((void**)&p_src2,  g_src2);
    cudaGetSymbolAddress((void**)&p_dst2,  g_dst2);
    cudaGetSymbolAddress((void**)&p_x,     g_x);
    cudaGetSymbolAddress((void**)&p_wcT,   g_wcT);
    cudaGetSymbolAddress((void**)&p_avec,  g_avec);
    cudaGetSymbolAddress((void**)&p_pv0,   g_pv0);
    cudaGetSymbolAddress((void**)&p_pv1,   g_pv1);
    cudaGetSymbolAddress((void**)&p_comp,  g_comp);
    cudaGetSymbolAddress((void**)&p_prot,  g_prot);

    const int SM1 = (32*NA + 32*(GD+4)  + NA + 32) * 4;   // 76416 B
    const int SM2 = (32*NA + 32*(CD+4)  + NA + 32) * 4;   // 84608 B
    cudaFuncSetAttribute(k_attn<GD>, cudaFuncAttributeMaxDynamicSharedMemorySize, SM1);
    cudaFuncSetAttribute(k_attn<CD>, cudaFuncAttributeMaxDynamicSharedMemorySize, SM2);

    static cudaStream_t s2 = nullptr;
    static cudaEvent_t evFork = nullptr, evAdj = nullptr, evJoin = nullptr;
    if (!s2){
        cudaStreamCreateWithFlags(&s2, cudaStreamNonBlocking);
        cudaEventCreateWithFlags(&evFork, cudaEventDisableTiming);
        cudaEventCreateWithFlags(&evAdj,  cudaEventDisableTiming);
        cudaEventCreateWithFlags(&evJoin, cudaEventDisableTiming);
    }

    // ---- common prep on main stream, then fork ----
    k_zero_acc<<<32, 256>>>();
    k_pack<<<128, 256>>>(W_gat, W_comp_w, W_att_w);
    cudaEventRecord(evFork, 0);
    cudaStreamWaitEvent(s2, evFork, 0);

    // ---- side stream: adjacency bitmask (overlaps Wh gemm), then amino path ----
    k_adjbits<<<BN*NA/256, 256, 0, s2>>>(adjacency);
    cudaEventRecord(evAdj, s2);
    k_conv<<<dim3(4,16,BB), dim3(32,8), 0, s2>>>(p_pv1, p_pv0, conv_w, conv_b, 0, amino, E_amino);
    k_conv<<<dim3(4,16,BB), dim3(32,8), 0, s2>>>(p_pv0, p_pv1, conv_w, conv_b, 1, nullptr, nullptr);
    k_conv<<<dim3(4,16,BB), dim3(32,8), 0, s2>>>(p_pv1, p_pv0, conv_w, conv_b, 2, nullptr, nullptr);
    k_pool<<<dim3(LA/32, BB), 256, 0, s2>>>(p_pv0, amino_mask, W_att_b, p_prot, LA);
    cudaEventRecord(evJoin, s2);

    // ---- atom path on main stream (src/dst fused into gemm epilogues) ----
    k_gemm<<<dim3(4,128), 256>>>(E_atom, p_wcat, p_wh, BN, NH*GD, CD, nullptr, 0, atoms, a_gat, 1);
    cudaStreamWaitEvent(0, evAdj, 0);
    k_attn<GD><<<dim3(NA/32, BB, NH), 256, SM1>>>(p_wh, NH*GD, p_src1, p_dst1, BN, p_multi, NH*GD);
    k_gemm<<<dim3(2,128), 256>>>(p_multi, W_go, p_wh2, BN, CD, NH*GD, nullptr, 0, nullptr, a_go, 2);
    k_attn<CD><<<dim3(NA/32, BB, 1), 256, SM2>>>(p_wh2, CD, p_src2, p_dst2, 0, p_x, CD);
    k_gemm<<<dim3(2,128), 256>>>(p_x, p_wcT, p_avec, BN, LATD, CD, W_comp_b, 1, nullptr, nullptr, 0);
    k_pool<<<dim3(NA/32, BB), 256>>>(p_avec, atoms_mask, W_att_b, p_comp, NA);

    // ---- join + head ----
    cudaStreamWaitEvent(0, evJoin, 0);
    k_final<<<BB, 256>>>(atoms_mask, amino_mask, pred_w, pred_b, outp);
}

// round 7
// speedup vs baseline: 1.7294x; 1.1174x over previous
#include <cuda_runtime.h>
#include <cstdint>
#include <math.h>

// ---------------- problem constants ----------------
#define BB   16
#define NA   512
#define LA   1024
#define CD   128
#define GD   64
#define NH   4
#define LATD 128
#define BN   (BB*NA)
#define WST  516            // score-row stride (floats): (4*row+col)%32 lane-permutation

// ---------------- device scratch ----------------
__device__ float    g_wcat [CD*NH*GD];
__device__ float    g_wh   [BN*NH*GD];
__device__ float    g_src1 [NH*BN];
__device__ float    g_dst1 [NH*BN];
__device__ float    g_multi[BN*NH*GD];
__device__ float    g_wh2  [BN*CD];
__device__ float    g_src2 [BN];
__device__ float    g_dst2 [BN];
__device__ float    g_x    [BN*CD];
__device__ float    g_wcT  [CD*LATD];
__device__ float    g_waT  [LATD*LATD];
__device__ float    g_avec [BN*LATD];
__device__ float    g_pv0  [BB*LA*CD];
__device__ float    g_pv1  [BB*LA*CD];
__device__ float    g_comp [BB*LATD];
__device__ float    g_prot [BB*LATD];
__device__ unsigned g_adjbits[BN*16];

__device__ __forceinline__ float lrelu_f(float x){ return x > 0.f ? x : 0.2f*x; }
__device__ __forceinline__ float elu_f(float x){ return x > 0.f ? x : (__expf(x) - 1.f); }

__device__ __forceinline__ uint32_t to_tf32(float f){
    uint32_t u; asm("cvt.rna.tf32.f32 %0, %1;" : "=r"(u) : "f"(f)); return u;
}
__device__ __forceinline__ void mma_tf32(float* d,
    uint32_t a0, uint32_t a1, uint32_t a2, uint32_t a3, uint32_t b0, uint32_t b1){
    asm volatile("mma.sync.aligned.m16n8k8.row.col.f32.tf32.tf32.f32 "
        "{%0,%1,%2,%3}, {%4,%5,%6,%7}, {%8,%9}, {%0,%1,%2,%3};"
        : "+f"(d[0]), "+f"(d[1]), "+f"(d[2]), "+f"(d[3])
        : "r"(a0), "r"(a1), "r"(a2), "r"(a3), "r"(b0), "r"(b1));
}

// ---------------- weight packing ----------------
__global__ void k_pack(const float* __restrict__ W_gat, const float* __restrict__ W_comp_w,
                       const float* __restrict__ W_att_w){
    int t = blockIdx.x*256 + threadIdx.x;
    if (t < CD*NH*GD){
        int k = t / (NH*GD), j = t % (NH*GD);
        int h = j / GD, f = j % GD;
        g_wcat[t] = W_gat[((size_t)h*CD + k)*GD + f];
    }
    if (t < CD*LATD){
        int k = t / LATD, l = t % LATD;
        g_wcT[t] = W_comp_w[(size_t)l*CD  + k];
        g_waT[t] = W_att_w [(size_t)l*LATD + k];
    }
}
__global__ void k_zero_acc(){
    int t = blockIdx.x*256 + threadIdx.x;
    if (t < BB*LATD){ g_comp[t] = 0.f; g_prot[t] = 0.f; }
    if (t < BN){ g_src2[t] = 0.f; g_dst2[t] = 0.f; }
}
__global__ void k_adjbits(const int* __restrict__ adj){
    int gid = blockIdx.x*256 + threadIdx.x;
    int v = adj[gid] > 0;
    unsigned m = __ballot_sync(0xffffffffu, v);
    if ((threadIdx.x & 31) == 0) g_adjbits[gid >> 5] = m;
}

// ---------------- tiled GEMM + fused src/dst projection epilogue ----------------
__global__ __launch_bounds__(256) void k_gemm(
    const float* __restrict__ A, const float* __restrict__ Bm, float* __restrict__ C,
    int M, int N, int K, const float* __restrict__ bias, int act,
    const int* __restrict__ rowmap, const float* __restrict__ aVec, int sdMode)
{
    __shared__ float As[16][68];
    __shared__ float Bs[16][64];
    int t = threadIdx.x;
    int row0 = blockIdx.y*64, col0 = blockIdx.x*64;
    int ty = t >> 4, tx = t & 15;
    float acc[4][4];
    #pragma unroll
    for (int i=0;i<4;i++){ acc[i][0]=0.f; acc[i][1]=0.f; acc[i][2]=0.f; acc[i][3]=0.f; }
    for (int k0=0;k0<K;k0+=16){
        #pragma unroll
        for (int i=t;i<1024;i+=256){
            int r=i>>4, c=i&15;
            int ar = row0 + r;
            if (rowmap) ar = rowmap[ar];
            As[c][r] = A[(size_t)ar*K + k0+c];
        }
        #pragma unroll
        for (int i=t;i<1024;i+=256){ int r=i>>6, c=i&63; Bs[r][c] = Bm[(size_t)(k0+r)*N + col0+c]; }
        __syncthreads();
        #pragma unroll
        for (int kk=0;kk<16;kk++){
            float4 a4 = *(const float4*)&As[kk][ty*4];
            float4 b4 = *(const float4*)&Bs[kk][tx*4];
            const float* ap = (const float*)&a4;
            const float* bp = (const float*)&b4;
            #pragma unroll
            for (int i=0;i<4;i++)
                #pragma unroll
                for (int j=0;j<4;j++) acc[i][j] += ap[i]*bp[j];
        }
        __syncthreads();
    }
    #pragma unroll
    for (int i=0;i<4;i++){
        int r = row0 + ty*4 + i;
        #pragma unroll
        for (int j=0;j<4;j++){
            int c = col0 + tx*4 + j;
            float v = acc[i][j];
            if (bias) v += bias[c];
            if (act)  v = lrelu_f(v);
            C[(size_t)r*N + c] = v;
        }
    }
    if (sdMode){
        int c0 = tx*4;
        float4 as4, ad4;
        if (sdMode == 1){
            const float* aP = aVec + (size_t)(col0 >> 6)*128;
            as4 = *(const float4*)&aP[c0];
            ad4 = *(const float4*)&aP[64 + c0];
        } else {
            as4 = *(const float4*)&aVec[col0 + c0];
            ad4 = *(const float4*)&aVec[128 + col0 + c0];
        }
        #pragma unroll
        for (int i=0;i<4;i++){
            float s = acc[i][0]*as4.x + acc[i][1]*as4.y + acc[i][2]*as4.z + acc[i][3]*as4.w;
            float d = acc[i][0]*ad4.x + acc[i][1]*ad4.y + acc[i][2]*ad4.z + acc[i][3]*ad4.w;
            #pragma unroll
            for (int o=8;o;o>>=1){
                s += __shfl_xor_sync(0xffffffffu, s, o);
                d += __shfl_xor_sync(0xffffffffu, d, o);
            }
            if (tx == 0){
                int r = row0 + ty*4 + i;
                if (sdMode == 1){
                    int h = col0 >> 6;
                    g_src1[(size_t)h*BN + r] = s;
                    g_dst1[(size_t)h*BN + r] = d;
                } else {
                    atomicAdd(&g_src2[r], s);
                    atomicAdd(&g_dst2[r], d);
                }
            }
        }
    }
}

// ---------------- fused GAT attention: score phase + tf32 mma.sync AV ----------------
// 32 rows/block, 256 threads (8 warps). Scores stored tf32-rounded, stride WST.
// Warp w: row-tile (w&1)*16, col-tile base (w>>1)*16; FDIM=128 also handles +64.
template<int FDIM>
__global__ __launch_bounds__(256) void k_attn(
    const float* __restrict__ Wh, int whStride,
    const float* __restrict__ src, const float* __restrict__ dst, int headStride,
    float* __restrict__ out, int outStride)
{
    constexpr int PAD = FDIM + 4;        // (4*k+n)%32 lane-permutation for B frags
    constexpr int FG  = FDIM / 4;
    constexpr int NCT = FDIM / 64;       // 16-col tile groups per warp (1 or 2)
    extern __shared__ float sm[];
    float* w    = sm;                    // [32][WST] tf32-rounded exp scores
    float* whs  = w + 32*WST;            // [32][PAD] tf32 Wh tile
    float* dsts = whs + 32*PAD;          // [512]
    float* zz   = dsts + NA;             // [32]
    uint32_t* w_u   = (uint32_t*)w;
    uint32_t* whs_u = (uint32_t*)whs;

    const int b = blockIdx.y, h = blockIdx.z;
    const int row0 = blockIdx.x * 32;
    const int t = threadIdx.x;
    const int wid = t >> 5, lane = t & 31;

    const float* srcp = src + (size_t)h*headStride + (size_t)b*NA;
    const float* dstp = dst + (size_t)h*headStride + (size_t)b*NA;
    const float* whp  = Wh  + (size_t)b*NA*whStride + h*GD;
    float*       outp = out + ((size_t)b*NA + row0)*outStride + h*GD;

    for (int j=t; j<NA; j+=256) dsts[j] = dstp[j];
    __syncthreads();

    // score phase: mask + leaky + exp + row-sum; store tf32-rounded exp
    const unsigned* bitsbase = g_adjbits + (size_t)(b*NA + row0)*16;
    #pragma unroll
    for (int rr=0; rr<4; rr++){
        int r = wid*4 + rr;
        float srcv = srcp[row0 + r];
        const unsigned* br = bitsbase + (size_t)r*16;
        float s = 0.f;
        #pragma unroll
        for (int it=0; it<16; it++){
            unsigned m = br[it];
            int j = it*32 + lane;
            float e = srcv + dsts[j];
            e = e > 0.f ? e : 0.2f*e;
            float ev = ((m >> lane) & 1u) ? __expf(e) : 0.f;
            w_u[r*WST + j] = to_tf32(ev);
            s += ev;
        }
        #pragma unroll
        for (int o=16;o;o>>=1) s += __shfl_xor_sync(0xffffffffu,s,o);
        if (lane==0) zz[r] = 1.f / s;
    }

    // AV via m16n8k8 tf32 mma
    const int rbase = (wid & 1) * 16;
    const int cbase = (wid >> 1) * 16;
    const int r0 = lane >> 2, c0 = lane & 3;
    float acc[NCT][2][4];
    #pragma unroll
    for (int ct=0;ct<NCT;ct++)
        #pragma unroll
        for (int nb=0;nb<2;nb++)
            #pragma unroll
            for (int i=0;i<4;i++) acc[ct][nb][i] = 0.f;

    for (int jt=0; jt<NA; jt+=32){
        __syncthreads();
        #pragma unroll
        for (int i=t; i<32*FG; i+=256){
            int row = i / FG, c4 = i % FG;
            float4 v = *(const float4*)&whp[(size_t)(jt+row)*whStride + c4*4];
            whs_u[row*PAD + c4*4 + 0] = to_tf32(v.x);
            whs_u[row*PAD + c4*4 + 1] = to_tf32(v.y);
            whs_u[row*PAD + c4*4 + 2] = to_tf32(v.z);
            whs_u[row*PAD + c4*4 + 3] = to_tf32(v.w);
        }
        __syncthreads();
        #pragma unroll
        for (int kk=0; kk<32; kk+=8){
            uint32_t a0 = w_u[(rbase + r0)*WST     + jt + kk + c0];
            uint32_t a1 = w_u[(rbase + r0 + 8)*WST + jt + kk + c0];
            uint32_t a2 = w_u[(rbase + r0)*WST     + jt + kk + c0 + 4];
            uint32_t a3 = w_u[(rbase + r0 + 8)*WST + jt + kk + c0 + 4];
            #pragma unroll
            for (int ct=0; ct<NCT; ct++){
                int nb0 = cbase + ct*64;
                #pragma unroll
                for (int nb=0; nb<2; nb++){
                    int n0 = nb0 + nb*8;
                    uint32_t b0 = whs_u[(kk + c0)*PAD     + n0 + r0];
                    uint32_t b1 = whs_u[(kk + c0 + 4)*PAD + n0 + r0];
                    mma_tf32(acc[ct][nb], a0, a1, a2, a3, b0, b1);
                }
            }
        }
    }

    // epilogue: normalize + elu, write float2 pairs
    float invA = zz[rbase + r0];
    float invB = zz[rbase + r0 + 8];
    #pragma unroll
    for (int ct=0; ct<NCT; ct++){
        #pragma unroll
        for (int nb=0; nb<2; nb++){
            int col = cbase + ct*64 + nb*8 + 2*c0;
            float2 vA, vB;
            vA.x = elu_f(acc[ct][nb][0]*invA); vA.y = elu_f(acc[ct][nb][1]*invA);
            vB.x = elu_f(acc[ct][nb][2]*invB); vB.y = elu_f(acc[ct][nb][3]*invB);
            *(float2*)&outp[(size_t)(rbase + r0)*outStride + col]     = vA;
            *(float2*)&outp[(size_t)(rbase + r0 + 8)*outStride + col] = vB;
        }
    }
}

// ---------------- 11x11 SAME conv + relu, 8 y-outputs/thread ----------------
__global__ __launch_bounds__(256) void k_conv(
    const float* __restrict__ in, float* __restrict__ out,
    const float* __restrict__ wAll, const float* __restrict__ bAll, int layer,
    const int* __restrict__ aminoIdx, const float* __restrict__ E)
{
    __shared__ float tile[74][44];
    __shared__ float ws[121];
    int bx = blockIdx.x, by = blockIdx.y, bz = blockIdx.z;
    int tx = threadIdx.x, ty = threadIdx.y;
    int t = ty*32 + tx;
    if (t < 121) ws[t] = wAll[layer*121 + t];
    int x0 = bx*32 - 5, y0 = by*64 - 5;
    const float* inb = in + (size_t)bz*LA*CD;
    for (int idx=t; idx<74*42; idx+=256){
        int ly = idx/42, lx = idx%42;
        int gy = y0+ly, gx = x0+lx;
        float v = 0.f;
        if (gx>=0 && gx<CD && gy>=0 && gy<LA){
            if (aminoIdx) v = E[(size_t)aminoIdx[(size_t)bz*LA + gy]*CD + gx];
            else          v = inb[(size_t)gy*CD + gx];
        }
        tile[ly][lx] = v;
    }
    __syncthreads();
    float bb = bAll[layer];
    float acc[8];
    #pragma unroll
    for (int q=0;q<8;q++) acc[q] = bb;
    #pragma unroll
    for (int dx=0; dx<11; dx++){
        float rv[18];
        #pragma unroll
        for (int i=0;i<18;i++) rv[i] = tile[ty*8 + i][tx + dx];
        #pragma unroll
        for (int dy=0; dy<11; dy++){
            float wv = ws[dy*11 + dx];
            #pragma unroll
            for (int q=0;q<8;q++) acc[q] += rv[q+dy]*wv;
        }
    }
    float* ob = out + (size_t)bz*LA*CD + (size_t)(by*64 + ty*8)*CD + bx*32 + tx;
    #pragma unroll
    for (int q=0;q<8;q++)
        ob[(size_t)q*CD] = fmaxf(acc[q], 0.f);
}

// ---------------- attention pool ----------------
__global__ __launch_bounds__(256) void k_pool(
    const float* __restrict__ vec, const float* __restrict__ mask,
    const float* __restrict__ ba, float* __restrict__ outAcc, int R)
{
    __shared__ float At[128*36];
    __shared__ float Bs[16*132];
    __shared__ float mks[32];
    int b = blockIdx.y, tile = blockIdx.x;
    int t = threadIdx.x;
    int ty = t >> 5, tx = t & 31;
    int r0 = tile*32;

    #pragma unroll
    for (int q=0;q<16;q++){
        int idx = q*256 + t;
        int r = idx >> 7, k = idx & 127;
        At[k*36 + r] = vec[((size_t)b*R + r0 + r)*LATD + k];
    }
    if (t < 32) mks[t] = mask[(size_t)b*R + r0 + t];

    float acc[4][4];
    #pragma unroll
    for (int i=0;i<4;i++){ acc[i][0]=0.f; acc[i][1]=0.f; acc[i][2]=0.f; acc[i][3]=0.f; }

    for (int k0=0; k0<LATD; k0+=16){
        __syncthreads();
        #pragma unroll
        for (int q=0;q<8;q++){
            int idx = q*256 + t;
            int kk = idx >> 7, f = idx & 127;
            Bs[kk*132 + f] = g_waT[(size_t)(k0+kk)*LATD + f];
        }
        __syncthreads();
        #pragma unroll
        for (int kk=0;kk<16;kk++){
            float4 a4 = *(const float4*)&At[(k0+kk)*36 + ty*4];
            float4 b4 = *(const float4*)&Bs[kk*132 + tx*4];
            const float* ap = (const float*)&a4; const float* bp = (const float*)&b4;
            #pragma unroll
            for (int i=0;i<4;i++)
                #pragma unroll
                for (int j=0;j<4;j++) acc[i][j] += ap[i]*bp[j];
        }
    }
    float4 bias4 = *(const float4*)&ba[tx*4];
    const float* bp = (const float*)&bias4;
    float part[4];
    #pragma unroll
    for (int c=0;c<4;c++){
        float s = 0.f;
        #pragma unroll
        for (int i=0;i<4;i++){
            float v = lrelu_f(acc[i][c] + bp[c]);
            s += v * mks[ty*4 + i];
        }
        part[c] = s;
    }
    __syncthreads();
    float* red = Bs;
    *(float4*)&red[ty*132 + tx*4] = make_float4(part[0], part[1], part[2], part[3]);
    __syncthreads();
    if (t < 128){
        float s = 0.f;
        #pragma unroll
        for (int g=0; g<8; g++) s += red[g*132 + t];
        atomicAdd(&outAcc[(size_t)b*LATD + t], s);
    }
}

// ---------------- final head ----------------
__global__ void k_final(const float* __restrict__ amask, const float* __restrict__ pmask,
                        const float* __restrict__ pw, const float* __restrict__ pb,
                        float* __restrict__ outp)
{
    int b = blockIdx.x, t = threadIdx.x;
    __shared__ float red[256];
    __shared__ float sums[2];
    float sa = 0.f;
    for (int i=t; i<NA; i+=256) sa += amask[(size_t)b*NA + i];
    red[t] = sa; __syncthreads();
    for (int o=128;o;o>>=1){ if (t<o) red[t] += red[t+o]; __syncthreads(); }
    if (t==0) sums[0] = red[0];
    __syncthreads();
    float sp = 0.f;
    for (int i=t; i<LA; i+=256) sp += pmask[(size_t)b*LA + i];
    red[t] = sp; __syncthreads();
    for (int o=128;o;o>>=1){ if (t<o) red[t] += red[t+o]; __syncthreads(); }
    if (t==0) sums[1] = red[0];
    __syncthreads();
    float v = (t < LATD) ? g_comp[(size_t)b*LATD + t] / sums[0]
                         : g_prot[(size_t)b*LATD + (t-LATD)] / sums[1];
    v = lrelu_f(lrelu_f(v));
    red[t] = v * pw[t]; __syncthreads();
    for (int o=128;o;o>>=1){ if (t<o) red[t] += red[t+o]; __syncthreads(); }
    if (t==0) outp[b] = red[0] + pb[0];
}

// ---------------- launch (2-stream fork/join) ----------------
extern "C" void kernel_launch(void* const* d_in, const int* in_sizes, int n_in,
                              void* d_out, int out_size)
{
    const int*   atoms      = (const int*)  d_in[0];
    const float* atoms_mask = (const float*)d_in[1];
    const int*   adjacency  = (const int*)  d_in[2];
    const int*   amino      = (const int*)  d_in[3];
    const float* amino_mask = (const float*)d_in[4];
    const float* E_atom     = (const float*)d_in[5];
    const float* E_amino    = (const float*)d_in[6];
    const float* W_gat      = (const float*)d_in[7];
    const float* a_gat      = (const float*)d_in[8];
    const float* W_go       = (const float*)d_in[9];
    const float* a_go       = (const float*)d_in[10];
    const float* W_comp_w   = (const float*)d_in[11];
    const float* W_comp_b   = (const float*)d_in[12];
    const float* conv_w     = (const float*)d_in[13];
    const float* conv_b     = (const float*)d_in[14];
    const float* W_att_w    = (const float*)d_in[15];
    const float* W_att_b    = (const float*)d_in[16];
    const float* pred_w     = (const float*)d_in[17];
    const float* pred_b     = (const float*)d_in[18];
    float* outp = (float*)d_out;

    float *p_wcat, *p_wh, *p_src1, *p_dst1, *p_multi, *p_wh2, *p_src2, *p_dst2;
    float *p_x, *p_wcT, *p_avec, *p_pv0, *p_pv1, *p_comp, *p_prot;
    cudaGetSymbolAddress((void**)&p_wcat,  g_wcat);
    cudaGetSymbolAddress((void**)&p_wh,    g_wh);
    cudaGetSymbolAddress((void**)&p_src1,  g_src1);
    cudaGetSymbolAddress((void**)&p_dst1,  g_dst1);
    cudaGetSymbolAddress((void**)&p_multi, g_multi);
    cudaGetSymbolAddress((void**)&p_wh2,   g_wh2);
    cudaGetSymbolAddress((void**)&p_src2,  g_src2);
    cudaGetSymbolAddress((void**)&p_dst2,  g_dst2);
    cudaGetSymbolAddress((void**)&p_x,     g_x);
    cudaGetSymbolAddress((void**)&p_wcT,   g_wcT);
    cudaGetSymbolAddress((void**)&p_avec,  g_avec);
    cudaGetSymbolAddress((void**)&p_pv0,   g_pv0);
    cudaGetSymbolAddress((void**)&p_pv1,   g_pv1);
    cudaGetSymbolAddress((void**)&p_comp,  g_comp);
    cudaGetSymbolAddress((void**)&p_prot,  g_prot);

    const int SM1 = (32*WST + 32*(GD+4)  + NA + 32) * 4;   // 76928 B
    const int SM2 = (32*WST + 32*(CD+4)  + NA + 32) * 4;   // 85120 B
    cudaFuncSetAttribute(k_attn<GD>, cudaFuncAttributeMaxDynamicSharedMemorySize, SM1);
    cudaFuncSetAttribute(k_attn<CD>, cudaFuncAttributeMaxDynamicSharedMemorySize, SM2);

    static cudaStream_t s2 = nullptr;
    static cudaEvent_t evFork = nullptr, evAdj = nullptr, evJoin = nullptr;
    if (!s2){
        cudaStreamCreateWithFlags(&s2, cudaStreamNonBlocking);
        cudaEventCreateWithFlags(&evFork, cudaEventDisableTiming);
        cudaEventCreateWithFlags(&evAdj,  cudaEventDisableTiming);
        cudaEventCreateWithFlags(&evJoin, cudaEventDisableTiming);
    }

    // ---- common prep on main stream, then fork ----
    k_zero_acc<<<32, 256>>>();
    k_pack<<<128, 256>>>(W_gat, W_comp_w, W_att_w);
    cudaEventRecord(evFork, 0);
    cudaStreamWaitEvent(s2, evFork, 0);

    // ---- side stream: adjacency bitmask, then amino path ----
    k_adjbits<<<BN*NA/256, 256, 0, s2>>>(adjacency);
    cudaEventRecord(evAdj, s2);
    k_conv<<<dim3(4,16,BB), dim3(32,8), 0, s2>>>(p_pv1, p_pv0, conv_w, conv_b, 0, amino, E_amino);
    k_conv<<<dim3(4,16,BB), dim3(32,8), 0, s2>>>(p_pv0, p_pv1, conv_w, conv_b, 1, nullptr, nullptr);
    k_conv<<<dim3(4,16,BB), dim3(32,8), 0, s2>>>(p_pv1, p_pv0, conv_w, conv_b, 2, nullptr, nullptr);
    k_pool<<<dim3(LA/32, BB), 256, 0, s2>>>(p_pv0, amino_mask, W_att_b, p_prot, LA);
    cudaEventRecord(evJoin, s2);

    // ---- atom path on main stream ----
    k_gemm<<<dim3(4,128), 256>>>(E_atom, p_wcat, p_wh, BN, NH*GD, CD, nullptr, 0, atoms, a_gat, 1);
    cudaStreamWaitEvent(0, evAdj, 0);
    k_attn<GD><<<dim3(NA/32, BB, NH), 256, SM1>>>(p_wh, NH*GD, p_src1, p_dst1, BN, p_multi, NH*GD);
    k_gemm<<<dim3(2,128), 256>>>(p_multi, W_go, p_wh2, BN, CD, NH*GD, nullptr, 0, nullptr, a_go, 2);
    k_attn<CD><<<dim3(NA/32, BB, 1), 256, SM2>>>(p_wh2, CD, p_src2, p_dst2, 0, p_x, CD);
    k_gemm<<<dim3(2,128), 256>>>(p_x, p_wcT, p_avec, BN, LATD, CD, W_comp_b, 1, nullptr, nullptr, 0);
    k_pool<<<dim3(NA/32, BB), 256>>>(p_avec, atoms_mask, W_att_b, p_comp, NA);

    // ---- join + head ----
    cudaStreamWaitEvent(0, evJoin, 0);
    k_final<<<BB, 256>>>(atoms_mask, amino_mask, pred_w, pred_b, outp);
}

// round 8
// speedup vs baseline: 2.1311x; 1.2322x over previous
#include <cuda_runtime.h>
#include <cstdint>
#include <math.h>

// ---------------- problem constants ----------------
#define BB   16
#define NA   512
#define LA   1024
#define CD   128
#define GD   64
#define NH   4
#define LATD 128
#define BN   (BB*NA)
#define WST  516            // score-row stride (floats): (4*row+col)%32 lane-permutation

// ---------------- device scratch ----------------
__device__ float    g_wcat [CD*NH*GD];
__device__ float    g_wh   [BN*NH*GD];
__device__ float    g_src1 [NH*BN];
__device__ float    g_dst1 [NH*BN];
__device__ float    g_multi[BN*NH*GD];
__device__ float    g_wh2  [BN*CD];
__device__ float    g_src2 [BN];
__device__ float    g_dst2 [BN];
__device__ float    g_x    [BN*CD];
__device__ float    g_wcT  [CD*LATD];
__device__ float    g_waT  [LATD*LATD];
__device__ float    g_avec [BN*LATD];
__device__ float    g_pv0  [BB*LA*CD];
__device__ float    g_pv1  [BB*LA*CD];
__device__ float    g_comp [BB*LATD];
__device__ float    g_prot [BB*LATD];
__device__ unsigned g_adjbits[BN*16];

__device__ __forceinline__ float lrelu_f(float x){ return x > 0.f ? x : 0.2f*x; }
__device__ __forceinline__ float elu_f(float x){ return x > 0.f ? x : (__expf(x) - 1.f); }

__device__ __forceinline__ uint32_t to_tf32(float f){
    uint32_t u; asm("cvt.rna.tf32.f32 %0, %1;" : "=r"(u) : "f"(f)); return u;
}
__device__ __forceinline__ void mma_tf32(float* d,
    uint32_t a0, uint32_t a1, uint32_t a2, uint32_t a3, uint32_t b0, uint32_t b1){
    asm volatile("mma.sync.aligned.m16n8k8.row.col.f32.tf32.tf32.f32 "
        "{%0,%1,%2,%3}, {%4,%5,%6,%7}, {%8,%9}, {%0,%1,%2,%3};"
        : "+f"(d[0]), "+f"(d[1]), "+f"(d[2]), "+f"(d[3])
        : "r"(a0), "r"(a1), "r"(a2), "r"(a3), "r"(b0), "r"(b1));
}

// ---------------- weight packing ----------------
__global__ void k_pack(const float* __restrict__ W_gat, const float* __restrict__ W_comp_w,
                       const float* __restrict__ W_att_w){
    int t = blockIdx.x*256 + threadIdx.x;
    if (t < CD*NH*GD){
        int k = t / (NH*GD), j = t % (NH*GD);
        int h = j / GD, f = j % GD;
        g_wcat[t] = W_gat[((size_t)h*CD + k)*GD + f];
    }
    if (t < CD*LATD){
        int k = t / LATD, l = t % LATD;
        g_wcT[t] = W_comp_w[(size_t)l*CD  + k];
        g_waT[t] = W_att_w [(size_t)l*LATD + k];
    }
}
__global__ void k_zero_acc(){
    int t = blockIdx.x*256 + threadIdx.x;
    if (t < BB*LATD){ g_comp[t] = 0.f; g_prot[t] = 0.f; }
    if (t < BN){ g_src2[t] = 0.f; g_dst2[t] = 0.f; }
    if (t < NH*BN){ g_src1[t] = 0.f; g_dst1[t] = 0.f; }
}
__global__ void k_adjbits(const int* __restrict__ adj){
    int gid = blockIdx.x*256 + threadIdx.x;
    int v = adj[gid] > 0;
    unsigned m = __ballot_sync(0xffffffffu, v);
    if ((threadIdx.x & 31) == 0) g_adjbits[gid >> 5] = m;
}

// ---------------- tf32 mma GEMM: C[M,N] = A[M,K] @ B[K,N]  (64x64 block tile) ----------------
// sdMode 1: also accumulate src1/dst1 (head = col/64) via atomicAdd (pre-zeroed).
// sdMode 2: accumulate src2/dst2.
__global__ __launch_bounds__(256) void k_gemm(
    const float* __restrict__ A, const float* __restrict__ Bm, float* __restrict__ C,
    int N, int K, const float* __restrict__ bias, int act,
    const int* __restrict__ rowmap, const float* __restrict__ aVec, int sdMode)
{
    __shared__ uint32_t As[64*36];     // [row][k] stride 36 (conflict-free A frags)
    __shared__ uint32_t Bs[32*68];     // [k][n]  stride 68
    int t = threadIdx.x;
    int row0 = blockIdx.y*64, col0 = blockIdx.x*64;
    int wid = t >> 5, lane = t & 31;
    int rbase = (wid & 3)*16, cbase = (wid >> 2)*32;
    int r0 = lane >> 2, c0 = lane & 3;
    float acc[4][4];
    #pragma unroll
    for (int nb=0;nb<4;nb++){ acc[nb][0]=0.f; acc[nb][1]=0.f; acc[nb][2]=0.f; acc[nb][3]=0.f; }

    for (int k0=0; k0<K; k0+=32){
        #pragma unroll
        for (int p=0;p<2;p++){
            int r = (t >> 3) + p*32;
            int gr = row0 + r;
            int ar = rowmap ? rowmap[gr] : gr;
            float4 v = *(const float4*)(A + (size_t)ar*K + k0 + (t & 7)*4);
            uint32_t* dst = &As[r*36 + (t & 7)*4];
            dst[0]=to_tf32(v.x); dst[1]=to_tf32(v.y); dst[2]=to_tf32(v.z); dst[3]=to_tf32(v.w);
        }
        #pragma unroll
        for (int p=0;p<2;p++){
            int kr = (t >> 4) + p*16;
            float4 v = *(const float4*)(Bm + (size_t)(k0+kr)*N + col0 + (t & 15)*4);
            uint32_t* dst = &Bs[kr*68 + (t & 15)*4];
            dst[0]=to_tf32(v.x); dst[1]=to_tf32(v.y); dst[2]=to_tf32(v.z); dst[3]=to_tf32(v.w);
        }
        __syncthreads();
        #pragma unroll
        for (int kk=0; kk<32; kk+=8){
            uint32_t a0 = As[(rbase+r0)*36   + kk + c0];
            uint32_t a1 = As[(rbase+r0+8)*36 + kk + c0];
            uint32_t a2 = As[(rbase+r0)*36   + kk + c0 + 4];
            uint32_t a3 = As[(rbase+r0+8)*36 + kk + c0 + 4];
            #pragma unroll
            for (int nb=0; nb<4; nb++){
                uint32_t b0 = Bs[(kk+c0)*68   + cbase + nb*8 + r0];
                uint32_t b1 = Bs[(kk+c0+4)*68 + cbase + nb*8 + r0];
                mma_tf32(acc[nb], a0, a1, a2, a3, b0, b1);
            }
        }
        __syncthreads();
    }

    // C epilogue
    int rA = row0 + rbase + r0, rB = rA + 8;
    #pragma unroll
    for (int nb=0; nb<4; nb++){
        int col = col0 + cbase + nb*8 + 2*c0;
        float b0v = 0.f, b1v = 0.f;
        if (bias){ b0v = bias[col]; b1v = bias[col+1]; }
        float v00 = acc[nb][0]+b0v, v01 = acc[nb][1]+b1v;
        float v10 = acc[nb][2]+b0v, v11 = acc[nb][3]+b1v;
        if (act){ v00=lrelu_f(v00); v01=lrelu_f(v01); v10=lrelu_f(v10); v11=lrelu_f(v11); }
        *(float2*)(C + (size_t)rA*N + col) = make_float2(v00, v01);
        *(float2*)(C + (size_t)rB*N + col) = make_float2(v10, v11);
    }

    // fused src/dst projection (raw acc, no bias/act)
    if (sdMode){
        float s0=0.f,d0=0.f,s1=0.f,d1=0.f;
        #pragma unroll
        for (int nb=0; nb<4; nb++){
            int col = col0 + cbase + nb*8 + 2*c0;
            const float* asv; const float* adv;
            if (sdMode == 1){
                int h = col >> 6, cc = col & 63;
                asv = aVec + (size_t)h*128 + cc;
                adv = aVec + (size_t)h*128 + 64 + cc;
            } else {
                asv = aVec + col;
                adv = aVec + 128 + col;
            }
            s0 += acc[nb][0]*asv[0] + acc[nb][1]*asv[1];
            d0 += acc[nb][0]*adv[0] + acc[nb][1]*adv[1];
            s1 += acc[nb][2]*asv[0] + acc[nb][3]*asv[1];
            d1 += acc[nb][2]*adv[0] + acc[nb][3]*adv[1];
        }
        #pragma unroll
        for (int o=1; o<4; o<<=1){
            s0 += __shfl_xor_sync(0xffffffffu, s0, o);
            d0 += __shfl_xor_sync(0xffffffffu, d0, o);
            s1 += __shfl_xor_sync(0xffffffffu, s1, o);
            d1 += __shfl_xor_sync(0xffffffffu, d1, o);
        }
        if (c0 == 0){
            if (sdMode == 1){
                int h = (col0 + cbase) >> 6;
                atomicAdd(&g_src1[(size_t)h*BN + rA], s0);
                atomicAdd(&g_dst1[(size_t)h*BN + rA], d0);
                atomicAdd(&g_src1[(size_t)h*BN + rB], s1);
                atomicAdd(&g_dst1[(size_t)h*BN + rB], d1);
            } else {
                atomicAdd(&g_src2[rA], s0); atomicAdd(&g_dst2[rA], d0);
                atomicAdd(&g_src2[rB], s1); atomicAdd(&g_dst2[rB], d1);
            }
        }
    }
}

// ---------------- fused GAT attention: score phase + tf32 mma AV ----------------
template<int FDIM>
__global__ __launch_bounds__(256) void k_attn(
    const float* __restrict__ Wh, int whStride,
    const float* __restrict__ src, const float* __restrict__ dst, int headStride,
    float* __restrict__ out, int outStride)
{
    constexpr int PAD = FDIM + 4;
    constexpr int FG  = FDIM / 4;
    constexpr int NCT = FDIM / 64;
    extern __shared__ float sm[];
    float* w    = sm;                    // [32][WST]
    float* whs  = w + 32*WST;            // [32][PAD]
    float* dsts = whs + 32*PAD;          // [512]
    float* zz   = dsts + NA;             // [32]
    uint32_t* w_u   = (uint32_t*)w;
    uint32_t* whs_u = (uint32_t*)whs;

    const int b = blockIdx.y, h = blockIdx.z;
    const int row0 = blockIdx.x * 32;
    const int t = threadIdx.x;
    const int wid = t >> 5, lane = t & 31;

    const float* srcp = src + (size_t)h*headStride + (size_t)b*NA;
    const float* dstp = dst + (size_t)h*headStride + (size_t)b*NA;
    const float* whp  = Wh  + (size_t)b*NA*whStride + h*GD;
    float*       outp = out + ((size_t)b*NA + row0)*outStride + h*GD;

    for (int j=t; j<NA; j+=256) dsts[j] = dstp[j];
    __syncthreads();

    const unsigned* bitsbase = g_adjbits + (size_t)(b*NA + row0)*16;
    #pragma unroll
    for (int rr=0; rr<4; rr++){
        int r = wid*4 + rr;
        float srcv = srcp[row0 + r];
        const unsigned* br = bitsbase + (size_t)r*16;
        float s = 0.f;
        #pragma unroll
        for (int it=0; it<16; it++){
            unsigned m = br[it];
            int j = it*32 + lane;
            float e = srcv + dsts[j];
            e = e > 0.f ? e : 0.2f*e;
            float ev = ((m >> lane) & 1u) ? __expf(e) : 0.f;
            w_u[r*WST + j] = to_tf32(ev);
            s += ev;
        }
        #pragma unroll
        for (int o=16;o;o>>=1) s += __shfl_xor_sync(0xffffffffu,s,o);
        if (lane==0) zz[r] = 1.f / s;
    }

    const int rbase = (wid & 1) * 16;
    const int cbase = (wid >> 1) * 16;
    const int r0 = lane >> 2, c0 = lane & 3;
    float acc[NCT][2][4];
    #pragma unroll
    for (int ct=0;ct<NCT;ct++)
        #pragma unroll
        for (int nb=0;nb<2;nb++)
            #pragma unroll
            for (int i=0;i<4;i++) acc[ct][nb][i] = 0.f;

    for (int jt=0; jt<NA; jt+=32){
        __syncthreads();
        #pragma unroll
        for (int i=t; i<32*FG; i+=256){
            int row = i / FG, c4 = i % FG;
            float4 v = *(const float4*)&whp[(size_t)(jt+row)*whStride + c4*4];
            whs_u[row*PAD + c4*4 + 0] = to_tf32(v.x);
            whs_u[row*PAD + c4*4 + 1] = to_tf32(v.y);
            whs_u[row*PAD + c4*4 + 2] = to_tf32(v.z);
            whs_u[row*PAD + c4*4 + 3] = to_tf32(v.w);
        }
        __syncthreads();
        #pragma unroll
        for (int kk=0; kk<32; kk+=8){
            uint32_t a0 = w_u[(rbase + r0)*WST     + jt + kk + c0];
            uint32_t a1 = w_u[(rbase + r0 + 8)*WST + jt + kk + c0];
            uint32_t a2 = w_u[(rbase + r0)*WST     + jt + kk + c0 + 4];
            uint32_t a3 = w_u[(rbase + r0 + 8)*WST + jt + kk + c0 + 4];
            #pragma unroll
            for (int ct=0; ct<NCT; ct++){
                int nb0 = cbase + ct*64;
                #pragma unroll
                for (int nb=0; nb<2; nb++){
                    int n0 = nb0 + nb*8;
                    uint32_t b0 = whs_u[(kk + c0)*PAD     + n0 + r0];
                    uint32_t b1 = whs_u[(kk + c0 + 4)*PAD + n0 + r0];
                    mma_tf32(acc[ct][nb], a0, a1, a2, a3, b0, b1);
                }
            }
        }
    }

    float invA = zz[rbase + r0];
    float invB = zz[rbase + r0 + 8];
    #pragma unroll
    for (int ct=0; ct<NCT; ct++){
        #pragma unroll
        for (int nb=0; nb<2; nb++){
            int col = cbase + ct*64 + nb*8 + 2*c0;
            float2 vA, vB;
            vA.x = elu_f(acc[ct][nb][0]*invA); vA.y = elu_f(acc[ct][nb][1]*invA);
            vB.x = elu_f(acc[ct][nb][2]*invB); vB.y = elu_f(acc[ct][nb][3]*invB);
            *(float2*)&outp[(size_t)(rbase + r0)*outStride + col]     = vA;
            *(float2*)&outp[(size_t)(rbase + r0 + 8)*outStride + col] = vB;
        }
    }
}

// ---------------- 11x11 SAME conv + relu, 8 y-outputs/thread ----------------
__global__ __launch_bounds__(256) void k_conv(
    const float* __restrict__ in, float* __restrict__ out,
    const float* __restrict__ wAll, const float* __restrict__ bAll, int layer,
    const int* __restrict__ aminoIdx, const float* __restrict__ E)
{
    __shared__ float tile[74][44];
    __shared__ float ws[121];
    int bx = blockIdx.x, by = blockIdx.y, bz = blockIdx.z;
    int tx = threadIdx.x, ty = threadIdx.y;
    int t = ty*32 + tx;
    if (t < 121) ws[t] = wAll[layer*121 + t];
    int x0 = bx*32 - 5, y0 = by*64 - 5;
    const float* inb = in + (size_t)bz*LA*CD;
    for (int idx=t; idx<74*42; idx+=256){
        int ly = idx/42, lx = idx%42;
        int gy = y0+ly, gx = x0+lx;
        float v = 0.f;
        if (gx>=0 && gx<CD && gy>=0 && gy<LA){
            if (aminoIdx) v = E[(size_t)aminoIdx[(size_t)bz*LA + gy]*CD + gx];
            else          v = inb[(size_t)gy*CD + gx];
        }
        tile[ly][lx] = v;
    }
    __syncthreads();
    float bb = bAll[layer];
    float acc[8];
    #pragma unroll
    for (int q=0;q<8;q++) acc[q] = bb;
    #pragma unroll
    for (int dx=0; dx<11; dx++){
        float rv[18];
        #pragma unroll
        for (int i=0;i<18;i++) rv[i] = tile[ty*8 + i][tx + dx];
        #pragma unroll
        for (int dy=0; dy<11; dy++){
            float wv = ws[dy*11 + dx];
            #pragma unroll
            for (int q=0;q<8;q++) acc[q] += rv[q+dy]*wv;
        }
    }
    float* ob = out + (size_t)bz*LA*CD + (size_t)(by*64 + ty*8)*CD + bx*32 + tx;
    #pragma unroll
    for (int q=0;q<8;q++)
        ob[(size_t)q*CD] = fmaxf(acc[q], 0.f);
}

// ---------------- attention pool (tf32 mma): acc[b] += sum_r mask_r*lrelu(vec_r@Wa^T+b) ----------------
__global__ __launch_bounds__(256) void k_pool(
    const float* __restrict__ vec, const float* __restrict__ mask,
    const float* __restrict__ ba, float* __restrict__ outAcc, int R)
{
    __shared__ uint32_t As[32*36];     // [row][k] stride 36
    __shared__ uint32_t Bs[32*132];    // [k][n=128] stride 132
    __shared__ float mks[32];
    int b = blockIdx.y;
    int r0tile = blockIdx.x*32;
    int t = threadIdx.x;
    int wid = t >> 5, lane = t & 31;
    int rbase = (wid & 1)*16, cbase = (wid >> 1)*32;
    int r0 = lane >> 2, c0 = lane & 3;

    if (t < 32) mks[t] = mask[(size_t)b*R + r0tile + t];

    float acc[4][4];
    #pragma unroll
    for (int nb=0;nb<4;nb++){ acc[nb][0]=0.f; acc[nb][1]=0.f; acc[nb][2]=0.f; acc[nb][3]=0.f; }

    for (int k0=0; k0<LATD; k0+=32){
        {
            int r = t >> 3;
            float4 v = *(const float4*)(vec + ((size_t)b*R + r0tile + r)*LATD + k0 + (t & 7)*4);
            uint32_t* dst = &As[r*36 + (t & 7)*4];
            dst[0]=to_tf32(v.x); dst[1]=to_tf32(v.y); dst[2]=to_tf32(v.z); dst[3]=to_tf32(v.w);
        }
        #pragma unroll
        for (int p=0;p<4;p++){
            int kr = (t >> 5) + p*8;
            float4 v = *(const float4*)(g_waT + (size_t)(k0+kr)*LATD + (t & 31)*4);
            uint32_t* dst = &Bs[kr*132 + (t & 31)*4];
            dst[0]=to_tf32(v.x); dst[1]=to_tf32(v.y); dst[2]=to_tf32(v.z); dst[3]=to_tf32(v.w);
        }
        __syncthreads();
        #pragma unroll
        for (int kk=0; kk<32; kk+=8){
            uint32_t a0 = As[(rbase+r0)*36   + kk + c0];
            uint32_t a1 = As[(rbase+r0+8)*36 + kk + c0];
            uint32_t a2 = As[(rbase+r0)*36   + kk + c0 + 4];
            uint32_t a3 = As[(rbase+r0+8)*36 + kk + c0 + 4];
            #pragma unroll
            for (int nb=0; nb<4; nb++){
                uint32_t b0 = Bs[(kk+c0)*132   + cbase + nb*8 + r0];
                uint32_t b1 = Bs[(kk+c0+4)*132 + cbase + nb*8 + r0];
                mma_tf32(acc[nb], a0, a1, a2, a3, b0, b1);
            }
        }
        __syncthreads();
    }

    float m0 = mks[rbase + r0], m1 = mks[rbase + r0 + 8];
    #pragma unroll
    for (int nb=0; nb<4; nb++){
        int col = cbase + nb*8 + 2*c0;
        float bb0 = ba[col], bb1 = ba[col+1];
        float cs0 = lrelu_f(acc[nb][0] + bb0)*m0 + lrelu_f(acc[nb][2] + bb0)*m1;
        float cs1 = lrelu_f(acc[nb][1] + bb1)*m0 + lrelu_f(acc[nb][3] + bb1)*m1;
        #pragma unroll
        for (int o=4; o<32; o<<=1){
            cs0 += __shfl_xor_sync(0xffffffffu, cs0, o);
            cs1 += __shfl_xor_sync(0xffffffffu, cs1, o);
        }
        if (r0 == 0){
            atomicAdd(&outAcc[(size_t)b*LATD + col],     cs0);
            atomicAdd(&outAcc[(size_t)b*LATD + col + 1], cs1);
        }
    }
}

// ---------------- final head ----------------
__global__ void k_final(const float* __restrict__ amask, const float* __restrict__ pmask,
                        const float* __restrict__ pw, const float* __restrict__ pb,
                        float* __restrict__ outp)
{
    int b = blockIdx.x, t = threadIdx.x;
    __shared__ float red[256];
    __shared__ float sums[2];
    float sa = 0.f;
    for (int i=t; i<NA; i+=256) sa += amask[(size_t)b*NA + i];
    red[t] = sa; __syncthreads();
    for (int o=128;o;o>>=1){ if (t<o) red[t] += red[t+o]; __syncthreads(); }
    if (t==0) sums[0] = red[0];
    __syncthreads();
    float sp = 0.f;
    for (int i=t; i<LA; i+=256) sp += pmask[(size_t)b*LA + i];
    red[t] = sp; __syncthreads();
    for (int o=128;o;o>>=1){ if (t<o) red[t] += red[t+o]; __syncthreads(); }
    if (t==0) sums[1] = red[0];
    __syncthreads();
    float v = (t < LATD) ? g_comp[(size_t)b*LATD + t] / sums[0]
                         : g_prot[(size_t)b*LATD + (t-LATD)] / sums[1];
    v = lrelu_f(lrelu_f(v));
    red[t] = v * pw[t]; __syncthreads();
    for (int o=128;o;o>>=1){ if (t<o) red[t] += red[t+o]; __syncthreads(); }
    if (t==0) outp[b] = red[0] + pb[0];
}

// ---------------- launch (2-stream fork/join) ----------------
extern "C" void kernel_launch(void* const* d_in, const int* in_sizes, int n_in,
                              void* d_out, int out_size)
{
    const int*   atoms      = (const int*)  d_in[0];
    const float* atoms_mask = (const float*)d_in[1];
    const int*   adjacency  = (const int*)  d_in[2];
    const int*   amino      = (const int*)  d_in[3];
    const float* amino_mask = (const float*)d_in[4];
    const float* E_atom     = (const float*)d_in[5];
    const float* E_amino    = (const float*)d_in[6];
    const float* W_gat      = (const float*)d_in[7];
    const float* a_gat      = (const float*)d_in[8];
    const float* W_go       = (const float*)d_in[9];
    const float* a_go       = (const float*)d_in[10];
    const float* W_comp_w   = (const float*)d_in[11];
    const float* W_comp_b   = (const float*)d_in[12];
    const float* conv_w     = (const float*)d_in[13];
    const float* conv_b     = (const float*)d_in[14];
    const float* W_att_w    = (const float*)d_in[15];
    const float* W_att_b    = (const float*)d_in[16];
    const float* pred_w     = (const float*)d_in[17];
    const float* pred_b     = (const float*)d_in[18];
    float* outp = (float*)d_out;

    float *p_wcat, *p_wh, *p_src1, *p_dst1, *p_multi, *p_wh2, *p_src2, *p_dst2;
    float *p_x, *p_wcT, *p_avec, *p_pv0, *p_pv1, *p_comp, *p_prot;
    cudaGetSymbolAddress((void**)&p_wcat,  g_wcat);
    cudaGetSymbolAddress((void**)&p_wh,    g_wh);
    cudaGetSymbolAddress((void**)&p_src1,  g_src1);
    cudaGetSymbolAddress((void**)&p_dst1,  g_dst1);
    cudaGetSymbolAddress((void**)&p_multi, g_multi);
    cudaGetSymbolAddress((void**)&p_wh2,   g_wh2);
    cudaGetSymbolAddress((void**)&p_src2,  g_src2);
    cudaGetSymbolAddress((void**)&p_dst2,  g_dst2);
    cudaGetSymbolAddress((void**)&p_x,     g_x);
    cudaGetSymbolAddress((void**)&p_wcT,   g_wcT);
    cudaGetSymbolAddress((void**)&p_avec,  g_avec);
    cudaGetSymbolAddress((void**)&p_pv0,   g_pv0);
    cudaGetSymbolAddress((void**)&p_pv1,   g_pv1);
    cudaGetSymbolAddress((void**)&p_comp,  g_comp);
    cudaGetSymbolAddress((void**)&p_prot,  g_prot);

    const int SM1 = (32*WST + 32*(GD+4)  + NA + 32) * 4;   // 76928 B
    const int SM2 = (32*WST + 32*(CD+4)  + NA + 32) * 4;   // 85120 B
    cudaFuncSetAttribute(k_attn<GD>, cudaFuncAttributeMaxDynamicSharedMemorySize, SM1);
    cudaFuncSetAttribute(k_attn<CD>, cudaFuncAttributeMaxDynamicSharedMemorySize, SM2);

    static cudaStream_t s2 = nullptr;
    static cudaEvent_t evFork = nullptr, evAdj = nullptr, evJoin = nullptr;
    if (!s2){
        cudaStreamCreateWithFlags(&s2, cudaStreamNonBlocking);
        cudaEventCreateWithFlags(&evFork, cudaEventDisableTiming);
        cudaEventCreateWithFlags(&evAdj,  cudaEventDisableTiming);
        cudaEventCreateWithFlags(&evJoin, cudaEventDisableTiming);
    }

    // ---- common prep on main stream, then fork ----
    k_zero_acc<<<128, 256>>>();
    k_pack<<<128, 256>>>(W_gat, W_comp_w, W_att_w);
    cudaEventRecord(evFork, 0);
    cudaStreamWaitEvent(s2, evFork, 0);

    // ---- side stream: adjacency bitmask, then amino path ----
    k_adjbits<<<BN*NA/256, 256, 0, s2>>>(adjacency);
    cudaEventRecord(evAdj, s2);
    k_conv<<<dim3(4,16,BB), dim3(32,8), 0, s2>>>(p_pv1, p_pv0, conv_w, conv_b, 0, amino, E_amino);
    k_conv<<<dim3(4,16,BB), dim3(32,8), 0, s2>>>(p_pv0, p_pv1, conv_w, conv_b, 1, nullptr, nullptr);
    k_conv<<<dim3(4,16,BB), dim3(32,8), 0, s2>>>(p_pv1, p_pv0, conv_w, conv_b, 2, nullptr, nullptr);
    k_pool<<<dim3(LA/32, BB), 256, 0, s2>>>(p_pv0, amino_mask, W_att_b, p_prot, LA);
    cudaEventRecord(evJoin, s2);

    // ---- atom path on main stream ----
    k_gemm<<<dim3(4,128), 256>>>(E_atom, p_wcat, p_wh, NH*GD, CD, nullptr, 0, atoms, a_gat, 1);
    cudaStreamWaitEvent(0, evAdj, 0);
    k_attn<GD><<<dim3(NA/32, BB, NH), 256, SM1>>>(p_wh, NH*GD, p_src1, p_dst1, BN, p_multi, NH*GD);
    k_gemm<<<dim3(2,128), 256>>>(p_multi, W_go, p_wh2, CD, NH*GD, nullptr, 0, nullptr, a_go, 2);
    k_attn<CD><<<dim3(NA/32, BB, 1), 256, SM2>>>(p_wh2, CD, p_src2, p_dst2, 0, p_x, CD);
    k_gemm<<<dim3(2,128), 256>>>(p_x, p_wcT, p_avec, LATD, CD, W_comp_b, 1, nullptr, nullptr, 0);
    k_pool<<<dim3(NA/32, BB), 256>>>(p_avec, atoms_mask, W_att_b, p_comp, NA);

    // ---- join + head ----
    cudaStreamWaitEvent(0, evJoin, 0);
    k_final<<<BB, 256>>>(atoms_mask, amino_mask, pred_w, pred_b, outp);
}

// round 9
// speedup vs baseline: 2.3180x; 1.0877x over previous
#include <cuda_runtime.h>
#include <cstdint>
#include <math.h>

// ---------------- problem constants ----------------
#define BB   16
#define NA   512
#define LA   1024
#define CD   128
#define GD   64
#define NH   4
#define LATD 128
#define BN   (BB*NA)
#define WST  516            // score-row stride (floats): (4*row+col)%32 lane-permutation

// ---------------- device scratch ----------------
__device__ float    g_wcat [CD*NH*GD];     // pre-rounded tf32
__device__ float    g_wgo  [NH*GD*CD];     // pre-rounded W_go copy
__device__ float    g_wh   [BN*NH*GD];     // rounded by gemm epi
__device__ float    g_src1 [NH*BN];
__device__ float    g_dst1 [NH*BN];
__device__ float    g_multi[BN*NH*GD];     // rounded by attn epi
__device__ float    g_wh2  [BN*CD];        // rounded
__device__ float    g_src2 [BN];
__device__ float    g_dst2 [BN];
__device__ float    g_x    [BN*CD];        // rounded
__device__ float    g_wcT  [CD*LATD];      // pre-rounded
__device__ float    g_waT  [LATD*LATD];    // pre-rounded
__device__ float    g_avec [BN*LATD];      // rounded
__device__ float    g_pv0  [BB*LA*CD];
__device__ float    g_pv1  [BB*LA*CD];
__device__ float    g_comp [BB*LATD];
__device__ float    g_prot [BB*LATD];
__device__ unsigned g_adjbits[BN*16];

__device__ __forceinline__ float lrelu_f(float x){ return x > 0.f ? x : 0.2f*x; }
__device__ __forceinline__ float elu_f(float x){ return x > 0.f ? x : (__expf(x) - 1.f); }

__device__ __forceinline__ uint32_t to_tf32(float f){
    uint32_t u; asm("cvt.rna.tf32.f32 %0, %1;" : "=r"(u) : "f"(f)); return u;
}
__device__ __forceinline__ float round_tf32(float f){ return __uint_as_float(to_tf32(f)); }
__device__ __forceinline__ void mma_tf32(float* d,
    uint32_t a0, uint32_t a1, uint32_t a2, uint32_t a3, uint32_t b0, uint32_t b1){
    asm volatile("mma.sync.aligned.m16n8k8.row.col.f32.tf32.tf32.f32 "
        "{%0,%1,%2,%3}, {%4,%5,%6,%7}, {%8,%9}, {%0,%1,%2,%3};"
        : "+f"(d[0]), "+f"(d[1]), "+f"(d[2]), "+f"(d[3])
        : "r"(a0), "r"(a1), "r"(a2), "r"(a3), "r"(b0), "r"(b1));
}

// ---------------- prep: zero accumulators + pack/pre-round weights ----------------
__global__ void k_pack(const float* __restrict__ W_gat, const float* __restrict__ W_comp_w,
                       const float* __restrict__ W_att_w, const float* __restrict__ W_go){
    int t = blockIdx.x*256 + threadIdx.x;    // 32768 total
    {   // Wcat[k][h*64+f] = W_gat[h][k][f], pre-rounded
        int k = t / (NH*GD), j = t % (NH*GD);
        int h = j / GD, f = j % GD;
        g_wcat[t] = round_tf32(W_gat[((size_t)h*CD + k)*GD + f]);
        g_wgo[t]  = round_tf32(W_go[t]);
    }
    if (t < CD*LATD){
        int k = t / LATD, l = t % LATD;
        g_wcT[t] = round_tf32(W_comp_w[(size_t)l*CD  + k]);
        g_waT[t] = round_tf32(W_att_w [(size_t)l*LATD + k]);
    }
    if (t < BB*LATD){ g_comp[t] = 0.f; g_prot[t] = 0.f; }
    if (t < BN){ g_src2[t] = 0.f; g_dst2[t] = 0.f; }
    { g_src1[t] = 0.f; g_dst1[t] = 0.f; }   // t < NH*BN == 32768
}
__global__ void k_adjbits(const int* __restrict__ adj){
    int gid = blockIdx.x*256 + threadIdx.x;
    int v = adj[gid] > 0;
    unsigned m = __ballot_sync(0xffffffffu, v);
    if ((threadIdx.x & 31) == 0) g_adjbits[gid >> 5] = m;
}

// ---------------- tf32 mma GEMM: C[M,N] = A[M,K] @ B[K,N]  (64x64 block tile) ----------------
// CVTA: convert A to tf32 during staging (raw fp32 input); B always pre-rounded.
// C stored tf32-pre-rounded. sdMode 1/2: fused src/dst accumulation via atomicAdd.
template<int CVTA>
__global__ __launch_bounds__(256) void k_gemm(
    const float* __restrict__ A, const float* __restrict__ Bm, float* __restrict__ C,
    int N, int K, const float* __restrict__ bias, int act,
    const int* __restrict__ rowmap, const float* __restrict__ aVec, int sdMode)
{
    __shared__ uint32_t As[64*36];
    __shared__ uint32_t Bs[32*68];
    int t = threadIdx.x;
    int row0 = blockIdx.y*64, col0 = blockIdx.x*64;
    int wid = t >> 5, lane = t & 31;
    int rbase = (wid & 3)*16, cbase = (wid >> 2)*32;
    int r0 = lane >> 2, c0 = lane & 3;
    float acc[4][4];
    #pragma unroll
    for (int nb=0;nb<4;nb++){ acc[nb][0]=0.f; acc[nb][1]=0.f; acc[nb][2]=0.f; acc[nb][3]=0.f; }

    for (int k0=0; k0<K; k0+=32){
        #pragma unroll
        for (int p=0;p<2;p++){
            int r = (t >> 3) + p*32;
            int gr = row0 + r;
            int ar = rowmap ? rowmap[gr] : gr;
            float4 v = *(const float4*)(A + (size_t)ar*K + k0 + (t & 7)*4);
            uint32_t* dst = &As[r*36 + (t & 7)*4];
            if (CVTA){
                dst[0]=to_tf32(v.x); dst[1]=to_tf32(v.y); dst[2]=to_tf32(v.z); dst[3]=to_tf32(v.w);
            } else {
                *(float4*)dst = v;
            }
        }
        #pragma unroll
        for (int p=0;p<2;p++){
            int kr = (t >> 4) + p*16;
            float4 v = *(const float4*)(Bm + (size_t)(k0+kr)*N + col0 + (t & 15)*4);
            *(float4*)&Bs[kr*68 + (t & 15)*4] = v;
        }
        __syncthreads();
        #pragma unroll
        for (int kk=0; kk<32; kk+=8){
            uint32_t a0 = As[(rbase+r0)*36   + kk + c0];
            uint32_t a1 = As[(rbase+r0+8)*36 + kk + c0];
            uint32_t a2 = As[(rbase+r0)*36   + kk + c0 + 4];
            uint32_t a3 = As[(rbase+r0+8)*36 + kk + c0 + 4];
            #pragma unroll
            for (int nb=0; nb<4; nb++){
                uint32_t b0 = Bs[(kk+c0)*68   + cbase + nb*8 + r0];
                uint32_t b1 = Bs[(kk+c0+4)*68 + cbase + nb*8 + r0];
                mma_tf32(acc[nb], a0, a1, a2, a3, b0, b1);
            }
        }
        __syncthreads();
    }

    int rA = row0 + rbase + r0, rB = rA + 8;
    #pragma unroll
    for (int nb=0; nb<4; nb++){
        int col = col0 + cbase + nb*8 + 2*c0;
        float b0v = 0.f, b1v = 0.f;
        if (bias){ b0v = bias[col]; b1v = bias[col+1]; }
        float v00 = acc[nb][0]+b0v, v01 = acc[nb][1]+b1v;
        float v10 = acc[nb][2]+b0v, v11 = acc[nb][3]+b1v;
        if (act){ v00=lrelu_f(v00); v01=lrelu_f(v01); v10=lrelu_f(v10); v11=lrelu_f(v11); }
        *(float2*)(C + (size_t)rA*N + col) = make_float2(round_tf32(v00), round_tf32(v01));
        *(float2*)(C + (size_t)rB*N + col) = make_float2(round_tf32(v10), round_tf32(v11));
    }

    if (sdMode){
        float s0=0.f,d0=0.f,s1=0.f,d1=0.f;
        #pragma unroll
        for (int nb=0; nb<4; nb++){
            int col = col0 + cbase + nb*8 + 2*c0;
            const float* asv; const float* adv;
            if (sdMode == 1){
                int h = col >> 6, cc = col & 63;
                asv = aVec + (size_t)h*128 + cc;
                adv = aVec + (size_t)h*128 + 64 + cc;
            } else {
                asv = aVec + col;
                adv = aVec + 128 + col;
            }
            s0 += acc[nb][0]*asv[0] + acc[nb][1]*asv[1];
            d0 += acc[nb][0]*adv[0] + acc[nb][1]*adv[1];
            s1 += acc[nb][2]*asv[0] + acc[nb][3]*asv[1];
            d1 += acc[nb][2]*adv[0] + acc[nb][3]*adv[1];
        }
        #pragma unroll
        for (int o=1; o<4; o<<=1){
            s0 += __shfl_xor_sync(0xffffffffu, s0, o);
            d0 += __shfl_xor_sync(0xffffffffu, d0, o);
            s1 += __shfl_xor_sync(0xffffffffu, s1, o);
            d1 += __shfl_xor_sync(0xffffffffu, d1, o);
        }
        if (c0 == 0){
            if (sdMode == 1){
                int h = (col0 + cbase) >> 6;
                atomicAdd(&g_src1[(size_t)h*BN + rA], s0);
                atomicAdd(&g_dst1[(size_t)h*BN + rA], d0);
                atomicAdd(&g_src1[(size_t)h*BN + rB], s1);
                atomicAdd(&g_dst1[(size_t)h*BN + rB], d1);
            } else {
                atomicAdd(&g_src2[rA], s0); atomicAdd(&g_dst2[rA], d0);
                atomicAdd(&g_src2[rB], s1); atomicAdd(&g_dst2[rB], d1);
            }
        }
    }
}

// ---------------- fused GAT attention: score phase + tf32 mma AV ----------------
// Wh is pre-rounded tf32 (no cvt in staging). Output stored pre-rounded.
template<int FDIM>
__global__ __launch_bounds__(256) void k_attn(
    const float* __restrict__ Wh, int whStride,
    const float* __restrict__ src, const float* __restrict__ dst, int headStride,
    float* __restrict__ out, int outStride)
{
    constexpr int PAD = FDIM + 4;
    constexpr int FG  = FDIM / 4;
    constexpr int NCT = FDIM / 64;
    extern __shared__ float sm[];
    float* w    = sm;                    // [32][WST]
    float* whs  = w + 32*WST;            // [32][PAD]
    float* dsts = whs + 32*PAD;          // [512]
    float* zz   = dsts + NA;             // [32]
    uint32_t* w_u   = (uint32_t*)w;
    uint32_t* whs_u = (uint32_t*)whs;

    const int b = blockIdx.y, h = blockIdx.z;
    const int row0 = blockIdx.x * 32;
    const int t = threadIdx.x;
    const int wid = t >> 5, lane = t & 31;

    const float* srcp = src + (size_t)h*headStride + (size_t)b*NA;
    const float* dstp = dst + (size_t)h*headStride + (size_t)b*NA;
    const float* whp  = Wh  + (size_t)b*NA*whStride + h*GD;
    float*       outp = out + ((size_t)b*NA + row0)*outStride + h*GD;

    for (int j=t; j<NA; j+=256) dsts[j] = dstp[j];
    __syncthreads();

    const unsigned* bitsbase = g_adjbits + (size_t)(b*NA + row0)*16;
    #pragma unroll
    for (int rr=0; rr<4; rr++){
        int r = wid*4 + rr;
        float srcv = srcp[row0 + r];
        const unsigned* br = bitsbase + (size_t)r*16;
        float s = 0.f;
        #pragma unroll
        for (int it=0; it<16; it++){
            unsigned m = br[it];
            int j = it*32 + lane;
            float e = srcv + dsts[j];
            e = e > 0.f ? e : 0.2f*e;
            float ev = ((m >> lane) & 1u) ? __expf(e) : 0.f;
            w_u[r*WST + j] = to_tf32(ev);
            s += ev;
        }
        #pragma unroll
        for (int o=16;o;o>>=1) s += __shfl_xor_sync(0xffffffffu,s,o);
        if (lane==0) zz[r] = 1.f / s;
    }

    const int rbase = (wid & 1) * 16;
    const int cbase = (wid >> 1) * 16;
    const int r0 = lane >> 2, c0 = lane & 3;
    float acc[NCT][2][4];
    #pragma unroll
    for (int ct=0;ct<NCT;ct++)
        #pragma unroll
        for (int nb=0;nb<2;nb++)
            #pragma unroll
            for (int i=0;i<4;i++) acc[ct][nb][i] = 0.f;

    for (int jt=0; jt<NA; jt+=32){
        __syncthreads();
        #pragma unroll
        for (int i=t; i<32*FG; i+=256){
            int row = i / FG, c4 = i % FG;
            float4 v = *(const float4*)&whp[(size_t)(jt+row)*whStride + c4*4];
            *(float4*)&whs_u[row*PAD + c4*4] = v;     // already tf32-rounded
        }
        __syncthreads();
        #pragma unroll
        for (int kk=0; kk<32; kk+=8){
            uint32_t a0 = w_u[(rbase + r0)*WST     + jt + kk + c0];
            uint32_t a1 = w_u[(rbase + r0 + 8)*WST + jt + kk + c0];
            uint32_t a2 = w_u[(rbase + r0)*WST     + jt + kk + c0 + 4];
            uint32_t a3 = w_u[(rbase + r0 + 8)*WST + jt + kk + c0 + 4];
            #pragma unroll
            for (int ct=0; ct<NCT; ct++){
                int nb0 = cbase + ct*64;
                #pragma unroll
                for (int nb=0; nb<2; nb++){
                    int n0 = nb0 + nb*8;
                    uint32_t b0 = whs_u[(kk + c0)*PAD     + n0 + r0];
                    uint32_t b1 = whs_u[(kk + c0 + 4)*PAD + n0 + r0];
                    mma_tf32(acc[ct][nb], a0, a1, a2, a3, b0, b1);
                }
            }
        }
    }

    float invA = zz[rbase + r0];
    float invB = zz[rbase + r0 + 8];
    #pragma unroll
    for (int ct=0; ct<NCT; ct++){
        #pragma unroll
        for (int nb=0; nb<2; nb++){
            int col = cbase + ct*64 + nb*8 + 2*c0;
            float2 vA, vB;
            vA.x = round_tf32(elu_f(acc[ct][nb][0]*invA));
            vA.y = round_tf32(elu_f(acc[ct][nb][1]*invA));
            vB.x = round_tf32(elu_f(acc[ct][nb][2]*invB));
            vB.y = round_tf32(elu_f(acc[ct][nb][3]*invB));
            *(float2*)&outp[(size_t)(rbase + r0)*outStride + col]     = vA;
            *(float2*)&outp[(size_t)(rbase + r0 + 8)*outStride + col] = vB;
        }
    }
}

// ---------------- 11x11 SAME conv + relu, 8 y-outputs/thread, transposed tile + float4 ----------------
__global__ __launch_bounds__(256) void k_conv(
    const float* __restrict__ in, float* __restrict__ out,
    const float* __restrict__ wAll, const float* __restrict__ bAll, int layer,
    const int* __restrict__ aminoIdx, const float* __restrict__ E, int roundOut)
{
    __shared__ float tileT[42][76];      // [x][y], stride 76 (≡12 mod 32: optimal LDS.128)
    __shared__ float ws[121];
    int bx = blockIdx.x, by = blockIdx.y, bz = blockIdx.z;
    int tx = threadIdx.x, ty = threadIdx.y;   // 32 x 8
    int t = ty*32 + tx;
    if (t < 121) ws[t] = wAll[layer*121 + t];
    int x0 = bx*32 - 5, y0 = by*64 - 5;
    const float* inb = in + (size_t)bz*LA*CD;
    for (int idx=t; idx<74*42; idx+=256){
        int ly = idx/42, lx = idx%42;
        int gy = y0+ly, gx = x0+lx;
        float v = 0.f;
        if (gx>=0 && gx<CD && gy>=0 && gy<LA){
            if (aminoIdx) v = E[(size_t)aminoIdx[(size_t)bz*LA + gy]*CD + gx];
            else          v = inb[(size_t)gy*CD + gx];
        }
        tileT[lx][ly] = v;
    }
    __syncthreads();
    float bb = bAll[layer];
    float acc[8];
    #pragma unroll
    for (int q=0;q<8;q++) acc[q] = bb;
    #pragma unroll
    for (int dx=0; dx<11; dx++){
        float4 rv4[5];
        #pragma unroll
        for (int g=0;g<5;g++) rv4[g] = *(const float4*)&tileT[tx+dx][ty*8 + g*4];
        const float* rv = (const float*)rv4;
        #pragma unroll
        for (int dy=0; dy<11; dy++){
            float wv = ws[dy*11 + dx];
            #pragma unroll
            for (int q=0;q<8;q++) acc[q] += rv[q+dy]*wv;
        }
    }
    float* ob = out + (size_t)bz*LA*CD + (size_t)(by*64 + ty*8)*CD + bx*32 + tx;
    #pragma unroll
    for (int q=0;q<8;q++){
        float v = fmaxf(acc[q], 0.f);
        ob[(size_t)q*CD] = roundOut ? round_tf32(v) : v;
    }
}

// ---------------- attention pool (tf32 mma) ----------------
// vec and g_waT are pre-rounded: no cvt in staging.
__global__ __launch_bounds__(256) void k_pool(
    const float* __restrict__ vec, const float* __restrict__ mask,
    const float* __restrict__ ba, float* __restrict__ outAcc, int R)
{
    __shared__ uint32_t As[32*36];
    __shared__ uint32_t Bs[32*132];
    __shared__ float mks[32];
    int b = blockIdx.y;
    int r0tile = blockIdx.x*32;
    int t = threadIdx.x;
    int wid = t >> 5, lane = t & 31;
    int rbase = (wid & 1)*16, cbase = (wid >> 1)*32;
    int r0 = lane >> 2, c0 = lane & 3;

    if (t < 32) mks[t] = mask[(size_t)b*R + r0tile + t];

    float acc[4][4];
    #pragma unroll
    for (int nb=0;nb<4;nb++){ acc[nb][0]=0.f; acc[nb][1]=0.f; acc[nb][2]=0.f; acc[nb][3]=0.f; }

    for (int k0=0; k0<LATD; k0+=32){
        {
            int r = t >> 3;
            float4 v = *(const float4*)(vec + ((size_t)b*R + r0tile + r)*LATD + k0 + (t & 7)*4);
            *(float4*)&As[r*36 + (t & 7)*4] = v;
        }
        #pragma unroll
        for (int p=0;p<4;p++){
            int kr = (t >> 5) + p*8;
            float4 v = *(const float4*)(g_waT + (size_t)(k0+kr)*LATD + (t & 31)*4);
            *(float4*)&Bs[kr*132 + (t & 31)*4] = v;
        }
        __syncthreads();
        #pragma unroll
        for (int kk=0; kk<32; kk+=8){
            uint32_t a0 = As[(rbase+r0)*36   + kk + c0];
            uint32_t a1 = As[(rbase+r0+8)*36 + kk + c0];
            uint32_t a2 = As[(rbase+r0)*36   + kk + c0 + 4];
            uint32_t a3 = As[(rbase+r0+8)*36 + kk + c0 + 4];
            #pragma unroll
            for (int nb=0; nb<4; nb++){
                uint32_t b0 = Bs[(kk+c0)*132   + cbase + nb*8 + r0];
                uint32_t b1 = Bs[(kk+c0+4)*132 + cbase + nb*8 + r0];
                mma_tf32(acc[nb], a0, a1, a2, a3, b0, b1);
            }
        }
        __syncthreads();
    }

    float m0 = mks[rbase + r0], m1 = mks[rbase + r0 + 8];
    #pragma unroll
    for (int nb=0; nb<4; nb++){
        int col = cbase + nb*8 + 2*c0;
        float bb0 = ba[col], bb1 = ba[col+1];
        float cs0 = lrelu_f(acc[nb][0] + bb0)*m0 + lrelu_f(acc[nb][2] + bb0)*m1;
        float cs1 = lrelu_f(acc[nb][1] + bb1)*m0 + lrelu_f(acc[nb][3] + bb1)*m1;
        #pragma unroll
        for (int o=4; o<32; o<<=1){
            cs0 += __shfl_xor_sync(0xffffffffu, cs0, o);
            cs1 += __shfl_xor_sync(0xffffffffu, cs1, o);
        }
        if (r0 == 0){
            atomicAdd(&outAcc[(size_t)b*LATD + col],     cs0);
            atomicAdd(&outAcc[(size_t)b*LATD + col + 1], cs1);
        }
    }
}

// ---------------- final head ----------------
__global__ void k_final(const float* __restrict__ amask, const float* __restrict__ pmask,
                        const float* __restrict__ pw, const float* __restrict__ pb,
                        float* __restrict__ outp)
{
    int b = blockIdx.x, t = threadIdx.x;
    __shared__ float red[256];
    __shared__ float sums[2];
    float sa = 0.f;
    for (int i=t; i<NA; i+=256) sa += amask[(size_t)b*NA + i];
    red[t] = sa; __syncthreads();
    for (int o=128;o;o>>=1){ if (t<o) red[t] += red[t+o]; __syncthreads(); }
    if (t==0) sums[0] = red[0];
    __syncthreads();
    float sp = 0.f;
    for (int i=t; i<LA; i+=256) sp += pmask[(size_t)b*LA + i];
    red[t] = sp; __syncthreads();
    for (int o=128;o;o>>=1){ if (t<o) red[t] += red[t+o]; __syncthreads(); }
    if (t==0) sums[1] = red[0];
    __syncthreads();
    float v = (t < LATD) ? g_comp[(size_t)b*LATD + t] / sums[0]
                         : g_prot[(size_t)b*LATD + (t-LATD)] / sums[1];
    v = lrelu_f(lrelu_f(v));
    red[t] = v * pw[t]; __syncthreads();
    for (int o=128;o;o>>=1){ if (t<o) red[t] += red[t+o]; __syncthreads(); }
    if (t==0) outp[b] = red[0] + pb[0];
}

// ---------------- launch (2-stream fork/join) ----------------
extern "C" void kernel_launch(void* const* d_in, const int* in_sizes, int n_in,
                              void* d_out, int out_size)
{
    const int*   atoms      = (const int*)  d_in[0];
    const float* atoms_mask = (const float*)d_in[1];
    const int*   adjacency  = (const int*)  d_in[2];
    const int*   amino      = (const int*)  d_in[3];
    const float* amino_mask = (const float*)d_in[4];
    const float* E_atom     = (const float*)d_in[5];
    const float* E_amino    = (const float*)d_in[6];
    const float* W_gat      = (const float*)d_in[7];
    const float* a_gat      = (const float*)d_in[8];
    const float* W_go       = (const float*)d_in[9];
    const float* a_go       = (const float*)d_in[10];
    const float* W_comp_w   = (const float*)d_in[11];
    const float* W_comp_b   = (const float*)d_in[12];
    const float* conv_w     = (const float*)d_in[13];
    const float* conv_b     = (const float*)d_in[14];
    const float* W_att_w    = (const float*)d_in[15];
    const float* W_att_b    = (const float*)d_in[16];
    const float* pred_w     = (const float*)d_in[17];
    const float* pred_b     = (const float*)d_in[18];
    float* outp = (float*)d_out;

    float *p_wcat, *p_wgo, *p_wh, *p_src1, *p_dst1, *p_multi, *p_wh2, *p_src2, *p_dst2;
    float *p_x, *p_wcT, *p_avec, *p_pv0, *p_pv1, *p_comp, *p_prot;
    cudaGetSymbolAddress((void**)&p_wcat,  g_wcat);
    cudaGetSymbolAddress((void**)&p_wgo,   g_wgo);
    cudaGetSymbolAddress((void**)&p_wh,    g_wh);
    cudaGetSymbolAddress((void**)&p_src1,  g_src1);
    cudaGetSymbolAddress((void**)&p_dst1,  g_dst1);
    cudaGetSymbolAddress((void**)&p_multi, g_multi);
    cudaGetSymbolAddress((void**)&p_wh2,   g_wh2);
    cudaGetSymbolAddress((void**)&p_src2,  g_src2);
    cudaGetSymbolAddress((void**)&p_dst2,  g_dst2);
    cudaGetSymbolAddress((void**)&p_x,     g_x);
    cudaGetSymbolAddress((void**)&p_wcT,   g_wcT);
    cudaGetSymbolAddress((void**)&p_avec,  g_avec);
    cudaGetSymbolAddress((void**)&p_pv0,   g_pv0);
    cudaGetSymbolAddress((void**)&p_pv1,   g_pv1);
    cudaGetSymbolAddress((void**)&p_comp,  g_comp);
    cudaGetSymbolAddress((void**)&p_prot,  g_prot);

    const int SM1 = (32*WST + 32*(GD+4)  + NA + 32) * 4;   // 76928 B
    const int SM2 = (32*WST + 32*(CD+4)  + NA + 32) * 4;   // 85120 B
    cudaFuncSetAttribute(k_attn<GD>, cudaFuncAttributeMaxDynamicSharedMemorySize, SM1);
    cudaFuncSetAttribute(k_attn<CD>, cudaFuncAttributeMaxDynamicSharedMemorySize, SM2);

    static cudaStream_t s2 = nullptr;
    static cudaEvent_t evFork = nullptr, evAdj = nullptr, evJoin = nullptr;
    if (!s2){
        cudaStreamCreateWithFlags(&s2, cudaStreamNonBlocking);
        cudaEventCreateWithFlags(&evFork, cudaEventDisableTiming);
        cudaEventCreateWithFlags(&evAdj,  cudaEventDisableTiming);
        cudaEventCreateWithFlags(&evJoin, cudaEventDisableTiming);
    }

    // ---- prep (zero + pack fused), then fork ----
    k_pack<<<128, 256>>>(W_gat, W_comp_w, W_att_w, W_go);
    cudaEventRecord(evFork, 0);
    cudaStreamWaitEvent(s2, evFork, 0);

    // ---- side stream: adjacency bitmask, then amino path ----
    k_adjbits<<<BN*NA/256, 256, 0, s2>>>(adjacency);
    cudaEventRecord(evAdj, s2);
    k_conv<<<dim3(4,16,BB), dim3(32,8), 0, s2>>>(p_pv1, p_pv0, conv_w, conv_b, 0, amino, E_amino, 0);
    k_conv<<<dim3(4,16,BB), dim3(32,8), 0, s2>>>(p_pv0, p_pv1, conv_w, conv_b, 1, nullptr, nullptr, 0);
    k_conv<<<dim3(4,16,BB), dim3(32,8), 0, s2>>>(p_pv1, p_pv0, conv_w, conv_b, 2, nullptr, nullptr, 1);
    k_pool<<<dim3(LA/32, BB), 256, 0, s2>>>(p_pv0, amino_mask, W_att_b, p_prot, LA);
    cudaEventRecord(evJoin, s2);

    // ---- atom path on main stream ----
    k_gemm<1><<<dim3(4,128), 256>>>(E_atom, p_wcat, p_wh, NH*GD, CD, nullptr, 0, atoms, a_gat, 1);
    cudaStreamWaitEvent(0, evAdj, 0);
    k_attn<GD><<<dim3(NA/32, BB, NH), 256, SM1>>>(p_wh, NH*GD, p_src1, p_dst1, BN, p_multi, NH*GD);
    k_gemm<0><<<dim3(2,128), 256>>>(p_multi, p_wgo, p_wh2, CD, NH*GD, nullptr, 0, nullptr, a_go, 2);
    k_attn<CD><<<dim3(NA/32, BB, 1), 256, SM2>>>(p_wh2, CD, p_src2, p_dst2, 0, p_x, CD);
    k_gemm<0><<<dim3(2,128), 256>>>(p_x, p_wcT, p_avec, LATD, CD, W_comp_b, 1, nullptr, nullptr, 0);
    k_pool<<<dim3(NA/32, BB), 256>>>(p_avec, atoms_mask, W_att_b, p_comp, NA);

    // ---- join + head ----
    cudaStreamWaitEvent(0, evJoin, 0);
    k_final<<<BB, 256>>>(atoms_mask, amino_mask, pred_w, pred_b, outp);
}